// round 2
// baseline (speedup 1.0000x reference)
#include <cuda_runtime.h>
#include <math.h>

// ---------------- problem constants ----------------
#define Bb   2
#define Ss   512
#define Hh   1024
#define NHh  16
#define Dd   64
#define Ll   4
#define FFf  4096
#define Vv   12800
#define NCc  14
#define SPAN 256
#define Rr   512           // 2*SPAN
#define Mm   (Bb*Ss)       // 1024 tokens
#define EPSLN 1e-7f

// ---------------- static device scratch (no allocation allowed) ----------------
__device__ float g_x   [Mm*Hh];
__device__ float g_rel [Rr*Hh];
__device__ float g_q   [Mm*Hh];
__device__ float g_k   [Mm*Hh];
__device__ float g_v   [Mm*Hh];
__device__ float g_posk[Rr*Hh];
__device__ float g_posq[Rr*Hh];
__device__ float g_sc  [(long)Bb*NHh*Ss*Ss];
__device__ float g_c2p [(long)Bb*NHh*Ss*Rr];
__device__ float g_p2c [(long)Bb*NHh*Ss*Rr];
__device__ float g_ctx [Mm*Hh];
__device__ float g_tmp [Mm*Hh];
__device__ float g_ff  [Mm*FFf];
__device__ float g_t   [Mm*Hh];
__device__ float g_logits[Mm*NCc];
__device__ int   g_ic2p[Ss*Ss];
__device__ int   g_ip2c[Ss*Ss];

// ---------------- helpers ----------------
__device__ __forceinline__ float block_sum(float v, float* red) {
    int tid = threadIdx.x;
    red[tid] = v; __syncthreads();
    #pragma unroll
    for (int s = 128; s > 0; s >>= 1) {
        if (tid < s) red[tid] += red[tid + s];
        __syncthreads();
    }
    float r = red[0]; __syncthreads();
    return r;
}

__device__ __forceinline__ float gelu_exact(float x) {
    return 0.5f * x * (1.0f + erff(x * 0.70710678118654752f));
}

// ---------------- relative-position bucket indices ----------------
__global__ void idx_kernel(int* c2pidx, int* p2cidx) {
    int t = blockIdx.x * blockDim.x + threadIdx.x;
    if (t >= Ss * Ss) return;
    int q = t / Ss, k = t % Ss;
    int rel = q - k;
    const int mid = 128;
    int ap = (rel < mid && rel > -mid) ? (mid - 1) : (rel < 0 ? -rel : rel);
    int bucket;
    if (ap <= mid) {
        bucket = rel;
    } else {
        // f32 replication of: ceil(log(ap/mid)/np.log(511/128)*(mid-1)) + mid
        const float divisor = (float)1.3843393288235763;  // np.log(511/128) demoted to f32
        float lp = ceilf(logf((float)ap / 128.0f) / divisor * 127.0f) + 128.0f;
        float sgn = (rel > 0) ? 1.0f : ((rel < 0) ? -1.0f : 0.0f);
        bucket = (int)(lp * sgn);   // trunc toward zero == astype(int32)
    }
    int c = bucket + SPAN;  c = c < 0 ? 0 : (c > 2 * SPAN - 1 ? 2 * SPAN - 1 : c);
    int p = -bucket + SPAN; p = p < 0 ? 0 : (p > 2 * SPAN - 1 ? 2 * SPAN - 1 : p);
    c2pidx[t] = c;
    p2cidx[t] = p;
}

// ---------------- embedding: x = LN(word_emb[ids]) * mask ----------------
__global__ void embed_kernel(const float* __restrict__ wemb, const int* __restrict__ ids,
                             const int* __restrict__ amask,
                             const float* __restrict__ s, const float* __restrict__ bb,
                             float* __restrict__ out) {
    __shared__ float red[256];
    int m = blockIdx.x, tid = threadIdx.x;
    const float* in = wemb + (long)ids[m] * Hh;
    float v[4];
    #pragma unroll
    for (int i = 0; i < 4; i++) v[i] = in[tid + i * 256];
    float sum = 0.f;
    #pragma unroll
    for (int i = 0; i < 4; i++) sum += v[i];
    float mu = block_sum(sum, red) * (1.0f / Hh);
    float var = 0.f;
    #pragma unroll
    for (int i = 0; i < 4; i++) { float d = v[i] - mu; var += d * d; }
    float vt = block_sum(var, red) * (1.0f / Hh);
    float inv = rsqrtf(vt + EPSLN);
    float mk = amask[m] ? 1.0f : 0.0f;
    #pragma unroll
    for (int i = 0; i < 4; i++) {
        int c = tid + i * 256;
        out[(long)m * Hh + c] = ((v[i] - mu) * inv * s[c] + bb[c]) * mk;
    }
}

// ---------------- plain row LayerNorm over H=1024 ----------------
__global__ void ln_kernel(const float* __restrict__ in, float* __restrict__ out,
                          const float* __restrict__ s, const float* __restrict__ bb) {
    __shared__ float red[256];
    int m = blockIdx.x, tid = threadIdx.x;
    const float* ir = in + (long)m * Hh;
    float v[4];
    #pragma unroll
    for (int i = 0; i < 4; i++) v[i] = ir[tid + i * 256];
    float sum = 0.f;
    #pragma unroll
    for (int i = 0; i < 4; i++) sum += v[i];
    float mu = block_sum(sum, red) * (1.0f / Hh);
    float var = 0.f;
    #pragma unroll
    for (int i = 0; i < 4; i++) { float d = v[i] - mu; var += d * d; }
    float vt = block_sum(var, red) * (1.0f / Hh);
    float inv = rsqrtf(vt + EPSLN);
    #pragma unroll
    for (int i = 0; i < 4; i++) {
        int c = tid + i * 256;
        out[(long)m * Hh + c] = (v[i] - mu) * inv * s[c] + bb[c];
    }
}

// ---------------- residual + LayerNorm: h = LN(h + y) ----------------
__global__ void add_ln_kernel(float* __restrict__ h, const float* __restrict__ y,
                              const float* __restrict__ s, const float* __restrict__ bb) {
    __shared__ float red[256];
    int m = blockIdx.x, tid = threadIdx.x;
    long base = (long)m * Hh;
    float v[4];
    #pragma unroll
    for (int i = 0; i < 4; i++) { int c = tid + i * 256; v[i] = h[base + c] + y[base + c]; }
    float sum = 0.f;
    #pragma unroll
    for (int i = 0; i < 4; i++) sum += v[i];
    float mu = block_sum(sum, red) * (1.0f / Hh);
    float var = 0.f;
    #pragma unroll
    for (int i = 0; i < 4; i++) { float d = v[i] - mu; var += d * d; }
    float vt = block_sum(var, red) * (1.0f / Hh);
    float inv = rsqrtf(vt + EPSLN);
    #pragma unroll
    for (int i = 0; i < 4; i++) {
        int c = tid + i * 256;
        h[base + c] = (v[i] - mu) * inv * s[c] + bb[c];
    }
}

// ---------------- generic SGEMM: C = A[M,K] @ W[K,N] + bias (+GELU) ----------------
#define BM 64
#define BN 64
#define BK 16
__global__ void gemm_bias_kernel(const float* __restrict__ A, const float* __restrict__ W,
                                 const float* __restrict__ bias, float* __restrict__ C,
                                 int M, int N, int K, int act) {
    __shared__ float As[BK][BM];
    __shared__ float Bs[BK][BN];
    int tid = threadIdx.x;
    int tx = tid & 15, ty = tid >> 4;
    int row0 = blockIdx.y * BM, col0 = blockIdx.x * BN;
    float acc[4][4] = {};
    for (int k0 = 0; k0 < K; k0 += BK) {
        #pragma unroll
        for (int i = 0; i < 4; i++) {
            int idx = tid + i * 256;
            int kk = idx >> 6, mm = idx & 63;
            As[kk][mm] = A[(long)(row0 + mm) * K + k0 + kk];
        }
        #pragma unroll
        for (int i = 0; i < 4; i++) {
            int idx = tid + i * 256;
            int kk = idx >> 6, nn = idx & 63;
            int col = col0 + nn;
            Bs[kk][nn] = (col < N) ? W[(long)(k0 + kk) * N + col] : 0.0f;
        }
        __syncthreads();
        #pragma unroll
        for (int kk = 0; kk < BK; kk++) {
            float a[4], b[4];
            #pragma unroll
            for (int i = 0; i < 4; i++) a[i] = As[kk][ty * 4 + i];
            #pragma unroll
            for (int j = 0; j < 4; j++) b[j] = Bs[kk][tx * 4 + j];
            #pragma unroll
            for (int i = 0; i < 4; i++)
                #pragma unroll
                for (int j = 0; j < 4; j++)
                    acc[i][j] += a[i] * b[j];
        }
        __syncthreads();
    }
    #pragma unroll
    for (int i = 0; i < 4; i++) {
        int r = row0 + ty * 4 + i;
        #pragma unroll
        for (int j = 0; j < 4; j++) {
            int c = col0 + tx * 4 + j;
            if (c < N) {
                float v = acc[i][j] + bias[c];
                if (act == 1) v = gelu_exact(v);
                C[(long)r * N + c] = v;
            }
        }
    }
}

// ---------------- batched SGEMM over (b,h); TB=1: C=A@B^T, TB=0: C=A@B --------
template <int TB>
__global__ void bgemm_kernel(const float* __restrict__ Ao, const float* __restrict__ Bo,
                             float* __restrict__ Co,
                             int M, int N, int K, int lda, int ldb, int ldc,
                             long sAb, long sAh, long sBb, long sBh, long sCb, long sCh) {
    int bh = blockIdx.z;
    int b = bh / NHh, h = bh % NHh;
    const float* A  = Ao + b * sAb + h * sAh;
    const float* Bm = Bo + b * sBb + h * sBh;
    float*       C  = Co + b * sCb + h * sCh;
    __shared__ float As[BK][BM];
    __shared__ float Bs[BK][BN];
    int tid = threadIdx.x;
    int tx = tid & 15, ty = tid >> 4;
    int row0 = blockIdx.y * BM, col0 = blockIdx.x * BN;
    float acc[4][4] = {};
    for (int k0 = 0; k0 < K; k0 += BK) {
        #pragma unroll
        for (int i = 0; i < 4; i++) {
            int idx = tid + i * 256;
            int kk = idx >> 6, mm = idx & 63;
            As[kk][mm] = A[(long)(row0 + mm) * lda + k0 + kk];
        }
        #pragma unroll
        for (int i = 0; i < 4; i++) {
            int idx = tid + i * 256;
            int kk = idx >> 6, nn = idx & 63;
            Bs[kk][nn] = TB ? Bm[(long)(col0 + nn) * ldb + k0 + kk]
                            : Bm[(long)(k0 + kk) * ldb + col0 + nn];
        }
        __syncthreads();
        #pragma unroll
        for (int kk = 0; kk < BK; kk++) {
            float a[4], bq[4];
            #pragma unroll
            for (int i = 0; i < 4; i++) a[i] = As[kk][ty * 4 + i];
            #pragma unroll
            for (int j = 0; j < 4; j++) bq[j] = Bs[kk][tx * 4 + j];
            #pragma unroll
            for (int i = 0; i < 4; i++)
                #pragma unroll
                for (int j = 0; j < 4; j++)
                    acc[i][j] += a[i] * bq[j];
        }
        __syncthreads();
    }
    #pragma unroll
    for (int i = 0; i < 4; i++)
        #pragma unroll
        for (int j = 0; j < 4; j++)
            C[(long)(row0 + ty * 4 + i) * ldc + col0 + tx * 4 + j] = acc[i][j];
}

// ---------------- fused gather + scale + mask + softmax (in place on scores) ----
__global__ void softmax_kernel(float* __restrict__ scores,
                               const float* __restrict__ c2p, const float* __restrict__ p2c,
                               const int* __restrict__ ic2p, const int* __restrict__ ip2c,
                               const int* __restrict__ amask) {
    __shared__ float sm[Ss];
    __shared__ float red[256];
    int q  = blockIdx.x;
    int bh = blockIdx.y;
    int b  = bh / NHh;
    int tid = threadIdx.x;
    const float inv_scale = 0.07216878364870322f;  // 1/sqrt(3*D)
    int maskq = amask[b * Ss + q];
    float* row = scores + ((long)bh * Ss + q) * Ss;
    const float* c2pr = c2p + ((long)bh * Ss + q) * Rr;
    const float* p2cb = p2c + (long)bh * Ss * Rr;

    for (int k = tid; k < Ss; k += 256) {
        float s;
        if (maskq && amask[b * Ss + k]) {
            // p2c is gathered with the index matrix evaluated at (k, q) (swapaxes in ref)
            s = (row[k] + c2pr[ic2p[q * Ss + k]] + p2cb[(long)k * Rr + ip2c[k * Ss + q]]) * inv_scale;
        } else {
            s = -INFINITY;
        }
        sm[k] = s;
    }
    __syncthreads();
    // max
    float mx = -INFINITY;
    for (int k = tid; k < Ss; k += 256) mx = fmaxf(mx, sm[k]);
    red[tid] = mx; __syncthreads();
    #pragma unroll
    for (int s = 128; s > 0; s >>= 1) {
        if (tid < s) red[tid] = fmaxf(red[tid], red[tid + s]);
        __syncthreads();
    }
    mx = red[0]; __syncthreads();
    if (mx == -INFINITY) {   // fully masked row -> zero probs
        for (int k = tid; k < Ss; k += 256) row[k] = 0.0f;
        return;
    }
    float sum = 0.f;
    for (int k = tid; k < Ss; k += 256) {
        float e = expf(sm[k] - mx);   // exp(-inf) == 0 for masked entries
        sm[k] = e;
        sum += e;
    }
    float tot = block_sum(sum, red);
    float inv = 1.0f / tot;
    for (int k = tid; k < Ss; k += 256) row[k] = sm[k] * inv;
}

// ---------------- loss + output assembly ----------------
__global__ void finalize_kernel(const float* __restrict__ logits, const int* __restrict__ labels,
                                const int* __restrict__ amask, float* __restrict__ out,
                                int out_size) {
    __shared__ float r1[256], r2[256];
    int tid = threadIdx.x;
    float ls = 0.f, ms = 0.f;
    for (int m = tid; m < Mm; m += 256) {
        const float* lr = logits + m * NCc;
        float mx = lr[0];
        #pragma unroll
        for (int c = 1; c < NCc; c++) mx = fmaxf(mx, lr[c]);
        float se = 0.f;
        #pragma unroll
        for (int c = 0; c < NCc; c++) se += expf(lr[c] - mx);
        float lse = logf(se) + mx;
        float nll = lse - lr[labels[m]];
        float mk = amask[m] ? 1.0f : 0.0f;
        ls += nll * mk;
        ms += mk;
    }
    r1[tid] = ls; r2[tid] = ms; __syncthreads();
    #pragma unroll
    for (int s = 128; s > 0; s >>= 1) {
        if (tid < s) { r1[tid] += r1[tid + s]; r2[tid] += r2[tid + s]; }
        __syncthreads();
    }
    float loss = r1[0] / fmaxf(r2[0], 1.0f);
    const int total = Mm * NCc;
    for (int i = tid; i < out_size; i += 256)
        out[i] = (i < total) ? logits[i] : loss;
}

// ---------------- host driver ----------------
extern "C" void kernel_launch(void* const* d_in, const int* in_sizes, int n_in,
                              void* d_out, int out_size) {
    const float* word_emb = (const float*)d_in[0];
    const float* emb_ln_s = (const float*)d_in[1];
    const float* emb_ln_b = (const float*)d_in[2];
    const float* rel_emb  = (const float*)d_in[3];
    const float* rel_ln_s = (const float*)d_in[4];
    const float* rel_ln_b = (const float*)d_in[5];
    const float* Wq = (const float*)d_in[6];
    const float* bq = (const float*)d_in[7];
    const float* Wk = (const float*)d_in[8];
    const float* bk = (const float*)d_in[9];
    const float* Wv = (const float*)d_in[10];
    const float* bv = (const float*)d_in[11];
    const float* Wo = (const float*)d_in[12];
    const float* bo = (const float*)d_in[13];
    const float* ln1_s = (const float*)d_in[14];
    const float* ln1_b = (const float*)d_in[15];
    const float* W1 = (const float*)d_in[16];
    const float* b1 = (const float*)d_in[17];
    const float* W2 = (const float*)d_in[18];
    const float* b2 = (const float*)d_in[19];
    const float* ln2_s = (const float*)d_in[20];
    const float* ln2_b = (const float*)d_in[21];
    const float* Wt = (const float*)d_in[22];
    const float* bt = (const float*)d_in[23];
    const float* tln_s = (const float*)d_in[24];
    const float* tln_b = (const float*)d_in[25];
    const float* Wd = (const float*)d_in[26];
    const float* bd = (const float*)d_in[27];
    const int* input_ids = (const int*)d_in[28];
    const int* amask     = (const int*)d_in[29];
    const int* labels    = (const int*)d_in[30];

    static bool init = false;
    static float *x, *rel, *q, *k, *v, *posk, *posq, *sc, *c2p, *p2c, *ctx, *tmp, *ff, *t, *logits;
    static int *ic2p, *ip2c;
    if (!init) {
        cudaGetSymbolAddress((void**)&x, g_x);
        cudaGetSymbolAddress((void**)&rel, g_rel);
        cudaGetSymbolAddress((void**)&q, g_q);
        cudaGetSymbolAddress((void**)&k, g_k);
        cudaGetSymbolAddress((void**)&v, g_v);
        cudaGetSymbolAddress((void**)&posk, g_posk);
        cudaGetSymbolAddress((void**)&posq, g_posq);
        cudaGetSymbolAddress((void**)&sc, g_sc);
        cudaGetSymbolAddress((void**)&c2p, g_c2p);
        cudaGetSymbolAddress((void**)&p2c, g_p2c);
        cudaGetSymbolAddress((void**)&ctx, g_ctx);
        cudaGetSymbolAddress((void**)&tmp, g_tmp);
        cudaGetSymbolAddress((void**)&ff, g_ff);
        cudaGetSymbolAddress((void**)&t, g_t);
        cudaGetSymbolAddress((void**)&logits, g_logits);
        cudaGetSymbolAddress((void**)&ic2p, g_ic2p);
        cudaGetSymbolAddress((void**)&ip2c, g_ip2c);
        init = true;
    }

    // precompute
    idx_kernel<<<(Ss * Ss + 255) / 256, 256>>>(ic2p, ip2c);
    ln_kernel<<<Rr, 256>>>(rel_emb, rel, rel_ln_s, rel_ln_b);
    embed_kernel<<<Mm, 256>>>(word_emb, input_ids, amask, emb_ln_s, emb_ln_b, x);

    const long sQKVb = (long)Ss * Hh;   // batch-b stride into token tensors
    const long sQKVh = Dd;              // head stride
    const long sSCb  = (long)NHh * Ss * Ss;
    const long sSCh  = (long)Ss * Ss;
    const long sPb   = (long)NHh * Ss * Rr;
    const long sPh   = (long)Ss * Rr;

    for (int l = 0; l < Ll; l++) {
        const float* Wq_l = Wq + (long)l * Hh * Hh;  const float* bq_l = bq + l * Hh;
        const float* Wk_l = Wk + (long)l * Hh * Hh;  const float* bk_l = bk + l * Hh;
        const float* Wv_l = Wv + (long)l * Hh * Hh;  const float* bv_l = bv + l * Hh;
        const float* Wo_l = Wo + (long)l * Hh * Hh;  const float* bo_l = bo + l * Hh;
        const float* W1_l = W1 + (long)l * Hh * FFf; const float* b1_l = b1 + l * FFf;
        const float* W2_l = W2 + (long)l * FFf * Hh; const float* b2_l = b2 + l * Hh;

        dim3 gHH(Hh / BN, Mm / BM);       // 16 x 16
        gemm_bias_kernel<<<gHH, 256>>>(x, Wq_l, bq_l, q, Mm, Hh, Hh, 0);
        gemm_bias_kernel<<<gHH, 256>>>(x, Wk_l, bk_l, k, Mm, Hh, Hh, 0);
        gemm_bias_kernel<<<gHH, 256>>>(x, Wv_l, bv_l, v, Mm, Hh, Hh, 0);
        dim3 gPos(Hh / BN, Rr / BM);      // 16 x 8
        gemm_bias_kernel<<<gPos, 256>>>(rel, Wk_l, bk_l, posk, Rr, Hh, Hh, 0);
        gemm_bias_kernel<<<gPos, 256>>>(rel, Wq_l, bq_l, posq, Rr, Hh, Hh, 0);

        // scores[b,h,q,k] = q . k
        bgemm_kernel<1><<<dim3(Ss / BN, Ss / BM, Bb * NHh), 256>>>(
            q, k, sc, Ss, Ss, Dd, Hh, Hh, Ss,
            sQKVb, sQKVh, sQKVb, sQKVh, sSCb, sSCh);
        // c2p[b,h,q,r] = q . pos_k
        bgemm_kernel<1><<<dim3(Rr / BN, Ss / BM, Bb * NHh), 256>>>(
            q, posk, c2p, Ss, Rr, Dd, Hh, Hh, Rr,
            sQKVb, sQKVh, 0L, (long)Dd, sPb, sPh);
        // p2c[b,h,k,r] = k . pos_q
        bgemm_kernel<1><<<dim3(Rr / BN, Ss / BM, Bb * NHh), 256>>>(
            k, posq, p2c, Ss, Rr, Dd, Hh, Hh, Rr,
            sQKVb, sQKVh, 0L, (long)Dd, sPb, sPh);

        softmax_kernel<<<dim3(Ss, Bb * NHh), 256>>>(sc, c2p, p2c, ic2p, ip2c, amask);

        // ctx[b,q,h,d] = probs @ v
        bgemm_kernel<0><<<dim3(Dd / BN, Ss / BM, Bb * NHh), 256>>>(
            sc, v, ctx, Ss, Dd, Ss, Ss, Hh, Hh,
            sSCb, sSCh, sQKVb, sQKVh, sQKVb, sQKVh);

        gemm_bias_kernel<<<gHH, 256>>>(ctx, Wo_l, bo_l, tmp, Mm, Hh, Hh, 0);
        add_ln_kernel<<<Mm, 256>>>(x, tmp, ln1_s + l * Hh, ln1_b + l * Hh);

        gemm_bias_kernel<<<dim3(FFf / BN, Mm / BM), 256>>>(x, W1_l, b1_l, ff, Mm, FFf, Hh, 1);
        gemm_bias_kernel<<<gHH, 256>>>(ff, W2_l, b2_l, tmp, Mm, Hh, FFf, 0);
        add_ln_kernel<<<Mm, 256>>>(x, tmp, ln2_s + l * Hh, ln2_b + l * Hh);
    }

    // head
    gemm_bias_kernel<<<dim3(Hh / BN, Mm / BM), 256>>>(x, Wt, bt, t, Mm, Hh, Hh, 1);
    ln_kernel<<<Mm, 256>>>(t, t, tln_s, tln_b);
    gemm_bias_kernel<<<dim3((NCc + BN - 1) / BN, Mm / BM), 256>>>(t, Wd, bd, logits, Mm, NCc, Hh, 0);

    finalize_kernel<<<1, 256>>>(logits, labels, amask, (float*)d_out, out_size);
}

// round 7
// speedup vs baseline: 1.4978x; 1.4978x over previous
#include <cuda_runtime.h>
#include <math.h>

// ---------------- problem constants ----------------
#define Bb   2
#define Ss   512
#define Hh   1024
#define NHh  16
#define Dd   64
#define Ll   4
#define FFf  4096
#define Vv   12800
#define NCc  14
#define SPAN 256
#define Rr   512           // 2*SPAN
#define Mm   (Bb*Ss)       // 1024 tokens
#define EPSLN 1e-7f

// ---------------- static device scratch (no allocation allowed) ----------------
__device__ float g_x   [Mm*Hh];
__device__ float g_rel [Rr*Hh];
__device__ float g_q   [Mm*Hh];
__device__ float g_k   [Mm*Hh];
__device__ float g_v   [Mm*Hh];
__device__ float g_posk[Rr*Hh];
__device__ float g_posq[Rr*Hh];
__device__ float g_sc  [(long)Bb*NHh*Ss*Ss];
__device__ float g_c2p [(long)Bb*NHh*Ss*Rr];
__device__ float g_p2c [(long)Bb*NHh*Ss*Rr];
__device__ float g_ctx [Mm*Hh];
__device__ float g_tmp [Mm*Hh];
__device__ float g_ff  [Mm*FFf];
__device__ float g_t   [Mm*Hh];
__device__ float g_part[4L*Mm*Hh];     // split-K partials
__device__ float g_logits[Mm*NCc];
__device__ int   g_ic2p[Ss*Ss];
__device__ int   g_ip2c[Ss*Ss];

// ---------------- helpers ----------------
__device__ __forceinline__ float block_sum(float v, float* red) {
    int tid = threadIdx.x;
    red[tid] = v; __syncthreads();
    #pragma unroll
    for (int s = 128; s > 0; s >>= 1) {
        if (tid < s) red[tid] += red[tid + s];
        __syncthreads();
    }
    float r = red[0]; __syncthreads();
    return r;
}

__device__ __forceinline__ float gelu_exact(float x) {
    return 0.5f * x * (1.0f + erff(x * 0.70710678118654752f));
}

// ================= 128x128 double-buffered SGEMM machinery =================
#define TBM 128
#define TBN 128
#define TBK 16
#define ASTR (TBM + 4)   // padded stride for transposed tiles

struct SmemNN { float As[2][TBK][ASTR]; float Bs[2][TBK][TBN]; };
struct SmemNT { float As[2][TBK][ASTR]; float Bs[2][TBK][ASTR]; };

// NN core: C[M,N] += A[M,lda(K)] @ W[K,N], k range [kstart,kend)
__device__ __forceinline__ void gemm_nn_core(
    SmemNN& sm, const float* __restrict__ A, const float* __restrict__ W,
    int N, int lda, int kstart, int kend, int row0, int col0, float acc[8][8]) {
    int tid = threadIdx.x;
    int ar = tid >> 2, ac = (tid & 3) << 2;
    int br = tid >> 5, bc = (tid & 31) << 2;
    int tx = tid & 15, ty = tid >> 4;
    const float* Ap  = A + (long)(row0 + ar) * lda;
    const float* Ap2 = Ap + 64L * lda;

    float4 pa0 = *(const float4*)(Ap  + kstart + ac);
    float4 pa1 = *(const float4*)(Ap2 + kstart + ac);
    float4 pb0 = *(const float4*)(W + (long)(kstart + br    ) * N + col0 + bc);
    float4 pb1 = *(const float4*)(W + (long)(kstart + br + 8) * N + col0 + bc);
    sm.As[0][ac+0][ar] = pa0.x; sm.As[0][ac+1][ar] = pa0.y;
    sm.As[0][ac+2][ar] = pa0.z; sm.As[0][ac+3][ar] = pa0.w;
    sm.As[0][ac+0][ar+64] = pa1.x; sm.As[0][ac+1][ar+64] = pa1.y;
    sm.As[0][ac+2][ar+64] = pa1.z; sm.As[0][ac+3][ar+64] = pa1.w;
    *(float4*)&sm.Bs[0][br][bc]     = pb0;
    *(float4*)&sm.Bs[0][br + 8][bc] = pb1;
    __syncthreads();

    int buf = 0;
    for (int k0 = kstart; k0 < kend; k0 += TBK) {
        int kn = k0 + TBK;
        bool more = kn < kend;
        if (more) {
            pa0 = *(const float4*)(Ap  + kn + ac);
            pa1 = *(const float4*)(Ap2 + kn + ac);
            pb0 = *(const float4*)(W + (long)(kn + br    ) * N + col0 + bc);
            pb1 = *(const float4*)(W + (long)(kn + br + 8) * N + col0 + bc);
        }
        #pragma unroll
        for (int kk = 0; kk < TBK; kk++) {
            float a[8], b[8];
            *(float4*)&a[0] = *(const float4*)&sm.As[buf][kk][ty * 4];
            *(float4*)&a[4] = *(const float4*)&sm.As[buf][kk][ty * 4 + 64];
            *(float4*)&b[0] = *(const float4*)&sm.Bs[buf][kk][tx * 4];
            *(float4*)&b[4] = *(const float4*)&sm.Bs[buf][kk][tx * 4 + 64];
            #pragma unroll
            for (int i = 0; i < 8; i++)
                #pragma unroll
                for (int j = 0; j < 8; j++)
                    acc[i][j] = fmaf(a[i], b[j], acc[i][j]);
        }
        if (more) {
            int nb = buf ^ 1;
            sm.As[nb][ac+0][ar] = pa0.x; sm.As[nb][ac+1][ar] = pa0.y;
            sm.As[nb][ac+2][ar] = pa0.z; sm.As[nb][ac+3][ar] = pa0.w;
            sm.As[nb][ac+0][ar+64] = pa1.x; sm.As[nb][ac+1][ar+64] = pa1.y;
            sm.As[nb][ac+2][ar+64] = pa1.z; sm.As[nb][ac+3][ar+64] = pa1.w;
            *(float4*)&sm.Bs[nb][br][bc]     = pb0;
            *(float4*)&sm.Bs[nb][br + 8][bc] = pb1;
        }
        __syncthreads();
        buf ^= 1;
    }
}

// NT core: C[M,N] += A[M,lda] @ B[N,ldb]^T, K elements
__device__ __forceinline__ void gemm_nt_core(
    SmemNT& sm, const float* __restrict__ A, const float* __restrict__ B,
    int lda, int ldb, int K, int row0, int col0, float acc[8][8]) {
    int tid = threadIdx.x;
    int ar = tid >> 2, ac = (tid & 3) << 2;
    int tx = tid & 15, ty = tid >> 4;
    const float* Ap  = A + (long)(row0 + ar) * lda;
    const float* Ap2 = Ap + 64L * lda;
    const float* Bp  = B + (long)(col0 + ar) * ldb;
    const float* Bp2 = Bp + 64L * ldb;

    float4 pa0 = *(const float4*)(Ap  + ac);
    float4 pa1 = *(const float4*)(Ap2 + ac);
    float4 pb0 = *(const float4*)(Bp  + ac);
    float4 pb1 = *(const float4*)(Bp2 + ac);
    sm.As[0][ac+0][ar] = pa0.x; sm.As[0][ac+1][ar] = pa0.y;
    sm.As[0][ac+2][ar] = pa0.z; sm.As[0][ac+3][ar] = pa0.w;
    sm.As[0][ac+0][ar+64] = pa1.x; sm.As[0][ac+1][ar+64] = pa1.y;
    sm.As[0][ac+2][ar+64] = pa1.z; sm.As[0][ac+3][ar+64] = pa1.w;
    sm.Bs[0][ac+0][ar] = pb0.x; sm.Bs[0][ac+1][ar] = pb0.y;
    sm.Bs[0][ac+2][ar] = pb0.z; sm.Bs[0][ac+3][ar] = pb0.w;
    sm.Bs[0][ac+0][ar+64] = pb1.x; sm.Bs[0][ac+1][ar+64] = pb1.y;
    sm.Bs[0][ac+2][ar+64] = pb1.z; sm.Bs[0][ac+3][ar+64] = pb1.w;
    __syncthreads();

    int buf = 0;
    for (int k0 = 0; k0 < K; k0 += TBK) {
        int kn = k0 + TBK;
        bool more = kn < K;
        if (more) {
            pa0 = *(const float4*)(Ap  + kn + ac);
            pa1 = *(const float4*)(Ap2 + kn + ac);
            pb0 = *(const float4*)(Bp  + kn + ac);
            pb1 = *(const float4*)(Bp2 + kn + ac);
        }
        #pragma unroll
        for (int kk = 0; kk < TBK; kk++) {
            float a[8], b[8];
            *(float4*)&a[0] = *(const float4*)&sm.As[buf][kk][ty * 4];
            *(float4*)&a[4] = *(const float4*)&sm.As[buf][kk][ty * 4 + 64];
            *(float4*)&b[0] = *(const float4*)&sm.Bs[buf][kk][tx * 4];
            *(float4*)&b[4] = *(const float4*)&sm.Bs[buf][kk][tx * 4 + 64];
            #pragma unroll
            for (int i = 0; i < 8; i++)
                #pragma unroll
                for (int j = 0; j < 8; j++)
                    acc[i][j] = fmaf(a[i], b[j], acc[i][j]);
        }
        if (more) {
            int nb = buf ^ 1;
            sm.As[nb][ac+0][ar] = pa0.x; sm.As[nb][ac+1][ar] = pa0.y;
            sm.As[nb][ac+2][ar] = pa0.z; sm.As[nb][ac+3][ar] = pa0.w;
            sm.As[nb][ac+0][ar+64] = pa1.x; sm.As[nb][ac+1][ar+64] = pa1.y;
            sm.As[nb][ac+2][ar+64] = pa1.z; sm.As[nb][ac+3][ar+64] = pa1.w;
            sm.Bs[nb][ac+0][ar] = pb0.x; sm.Bs[nb][ac+1][ar] = pb0.y;
            sm.Bs[nb][ac+2][ar] = pb0.z; sm.Bs[nb][ac+3][ar] = pb0.w;
            sm.Bs[nb][ac+0][ar+64] = pb1.x; sm.Bs[nb][ac+1][ar+64] = pb1.y;
            sm.Bs[nb][ac+2][ar+64] = pb1.z; sm.Bs[nb][ac+3][ar+64] = pb1.w;
        }
        __syncthreads();
        buf ^= 1;
    }
}

__device__ __forceinline__ void epilogue_bias(
    float* __restrict__ C, const float* __restrict__ bias, float acc[8][8],
    int row0, int col0, int ldc, int act) {
    int tid = threadIdx.x;
    int tx = tid & 15, ty = tid >> 4;
    #pragma unroll
    for (int ih = 0; ih < 2; ih++)
        #pragma unroll
        for (int i = 0; i < 4; i++) {
            int r = row0 + ty * 4 + i + ih * 64;
            #pragma unroll
            for (int jh = 0; jh < 2; jh++) {
                int c = col0 + tx * 4 + jh * 64;
                float4 o;
                o.x = acc[ih*4+i][jh*4+0] + bias[c+0];
                o.y = acc[ih*4+i][jh*4+1] + bias[c+1];
                o.z = acc[ih*4+i][jh*4+2] + bias[c+2];
                o.w = acc[ih*4+i][jh*4+3] + bias[c+3];
                if (act) {
                    o.x = gelu_exact(o.x); o.y = gelu_exact(o.y);
                    o.z = gelu_exact(o.z); o.w = gelu_exact(o.w);
                }
                *(float4*)(C + (long)r * ldc + c) = o;
            }
        }
}

__device__ __forceinline__ void epilogue_raw(
    float* __restrict__ C, float acc[8][8], int row0, int col0, int ldc) {
    int tid = threadIdx.x;
    int tx = tid & 15, ty = tid >> 4;
    #pragma unroll
    for (int ih = 0; ih < 2; ih++)
        #pragma unroll
        for (int i = 0; i < 4; i++) {
            int r = row0 + ty * 4 + i + ih * 64;
            #pragma unroll
            for (int jh = 0; jh < 2; jh++) {
                int c = col0 + tx * 4 + jh * 64;
                float4 o;
                o.x = acc[ih*4+i][jh*4+0]; o.y = acc[ih*4+i][jh*4+1];
                o.z = acc[ih*4+i][jh*4+2]; o.w = acc[ih*4+i][jh*4+3];
                *(float4*)(C + (long)r * ldc + c) = o;
            }
        }
}

// fused q/k/v + pos_k/pos_q projections (z=0..4)
__global__ __launch_bounds__(256, 2) void qkvpos_kernel(
    const float* __restrict__ x, const float* __restrict__ rel,
    const float* __restrict__ Wq, const float* __restrict__ Wk, const float* __restrict__ Wv,
    const float* __restrict__ bq, const float* __restrict__ bk, const float* __restrict__ bv,
    float* q, float* k, float* v, float* posk, float* posq) {
    __shared__ SmemNN sm;
    int z = blockIdx.z;
    const float *A, *W, *bias; float* C;
    if (z == 0)      { A = x;   W = Wq; bias = bq; C = q; }
    else if (z == 1) { A = x;   W = Wk; bias = bk; C = k; }
    else if (z == 2) { A = x;   W = Wv; bias = bv; C = v; }
    else if (z == 3) { if (blockIdx.y >= 4) return; A = rel; W = Wk; bias = bk; C = posk; }
    else             { if (blockIdx.y >= 4) return; A = rel; W = Wq; bias = bq; C = posq; }
    int row0 = blockIdx.y * TBM, col0 = blockIdx.x * TBN;
    float acc[8][8] = {};
    gemm_nn_core(sm, A, W, Hh, Hh, 0, Hh, row0, col0, acc);
    epilogue_bias(C, bias, acc, row0, col0, Hh, 0);
}

// generic single NN GEMM with bias (+GELU)
__global__ __launch_bounds__(256, 2) void gemm128_kernel(
    const float* __restrict__ A, const float* __restrict__ W,
    const float* __restrict__ bias, float* C, int N, int K, int act) {
    __shared__ SmemNN sm;
    int row0 = blockIdx.y * TBM, col0 = blockIdx.x * TBN;
    float acc[8][8] = {};
    gemm_nn_core(sm, A, W, N, K, 0, K, row0, col0, acc);
    epilogue_bias(C, bias, acc, row0, col0, N, act);
}

// split-K NN GEMM into partial buffers (deterministic; z = k-chunk)
__global__ __launch_bounds__(256, 2) void gemm128_split_kernel(
    const float* __restrict__ A, const float* __restrict__ W,
    float* P, int N, int K, int nsplit) {
    __shared__ SmemNN sm;
    int z = blockIdx.z;
    int kc = K / nsplit;
    int row0 = blockIdx.y * TBM, col0 = blockIdx.x * TBN;
    float acc[8][8] = {};
    gemm_nn_core(sm, A, W, N, K, z * kc, (z + 1) * kc, row0, col0, acc);
    int M = gridDim.y * TBM;
    float* C = P + (long)z * M * N;
    epilogue_raw(C, acc, row0, col0, N);
}

__global__ void reduce_bias_kernel(const float* __restrict__ P, const float* __restrict__ bias,
                                   float* __restrict__ C, int M, int N, int nsplit, int act) {
    int i = blockIdx.x * blockDim.x + threadIdx.x;
    long sz = (long)M * N;
    if (i >= sz) return;
    float s = 0.f;
    for (int p = 0; p < nsplit; p++) s += P[(long)p * sz + i];
    s += bias[i & (N - 1)];            // N is a power of two here (1024)
    if (act) s = gelu_exact(s);
    C[i] = s;
}

// fused scores / c2p / p2c NT batched GEMM (z = type*32 + bh)
__global__ __launch_bounds__(256, 2) void att_nt128_kernel(
    const float* __restrict__ q, const float* __restrict__ k,
    const float* __restrict__ posk, const float* __restrict__ posq,
    float* sc, float* c2p, float* p2c) {
    __shared__ SmemNT sm;
    int z = blockIdx.z;
    int type = z >> 5;
    int bh = z & 31;
    int b = bh >> 4, h = bh & 15;
    const float* A = ((type == 2) ? k : q) + (long)b * Ss * Hh + (long)h * Dd;
    const float* B;
    if (type == 0)      B = k    + (long)b * Ss * Hh + (long)h * Dd;
    else if (type == 1) B = posk + (long)h * Dd;
    else                B = posq + (long)h * Dd;
    float* C = (type == 0 ? sc : (type == 1 ? c2p : p2c)) + (long)bh * Ss * 512;
    int row0 = blockIdx.y * TBM, col0 = blockIdx.x * TBN;
    float acc[8][8] = {};
    gemm_nt_core(sm, A, B, Hh, Hh, Dd, row0, col0, acc);
    epilogue_raw(C, acc, row0, col0, 512);
}

// ---------------- relative-position bucket indices ----------------
__global__ void idx_kernel(int* c2pidx, int* p2cidx) {
    int t = blockIdx.x * blockDim.x + threadIdx.x;
    if (t >= Ss * Ss) return;
    int q = t / Ss, k = t % Ss;
    int rel = q - k;
    const int mid = 128;
    int ap = (rel < mid && rel > -mid) ? (mid - 1) : (rel < 0 ? -rel : rel);
    int bucket;
    if (ap <= mid) {
        bucket = rel;
    } else {
        const float divisor = (float)1.3843393288235763;  // np.log(511/128) as f32
        float lp = ceilf(logf((float)ap / 128.0f) / divisor * 127.0f) + 128.0f;
        float sgn = (rel > 0) ? 1.0f : ((rel < 0) ? -1.0f : 0.0f);
        bucket = (int)(lp * sgn);
    }
    int c = bucket + SPAN;  c = c < 0 ? 0 : (c > 2 * SPAN - 1 ? 2 * SPAN - 1 : c);
    int p = -bucket + SPAN; p = p < 0 ? 0 : (p > 2 * SPAN - 1 ? 2 * SPAN - 1 : p);
    c2pidx[t] = c;
    p2cidx[t] = p;
}

// ---------------- embedding: x = LN(word_emb[ids]) * mask ----------------
__global__ void embed_kernel(const float* __restrict__ wemb, const int* __restrict__ ids,
                             const int* __restrict__ amask,
                             const float* __restrict__ s, const float* __restrict__ bb,
                             float* __restrict__ out) {
    __shared__ float red[256];
    int m = blockIdx.x, tid = threadIdx.x;
    const float* in = wemb + (long)ids[m] * Hh;
    float v[4];
    #pragma unroll
    for (int i = 0; i < 4; i++) v[i] = in[tid + i * 256];
    float sum = 0.f;
    #pragma unroll
    for (int i = 0; i < 4; i++) sum += v[i];
    float mu = block_sum(sum, red) * (1.0f / Hh);
    float var = 0.f;
    #pragma unroll
    for (int i = 0; i < 4; i++) { float d = v[i] - mu; var += d * d; }
    float vt = block_sum(var, red) * (1.0f / Hh);
    float inv = rsqrtf(vt + EPSLN);
    float mk = amask[m] ? 1.0f : 0.0f;
    #pragma unroll
    for (int i = 0; i < 4; i++) {
        int c = tid + i * 256;
        out[(long)m * Hh + c] = ((v[i] - mu) * inv * s[c] + bb[c]) * mk;
    }
}

// ---------------- plain row LayerNorm over H=1024 ----------------
__global__ void ln_kernel(const float* __restrict__ in, float* __restrict__ out,
                          const float* __restrict__ s, const float* __restrict__ bb) {
    __shared__ float red[256];
    int m = blockIdx.x, tid = threadIdx.x;
    const float* ir = in + (long)m * Hh;
    float v[4];
    #pragma unroll
    for (int i = 0; i < 4; i++) v[i] = ir[tid + i * 256];
    float sum = 0.f;
    #pragma unroll
    for (int i = 0; i < 4; i++) sum += v[i];
    float mu = block_sum(sum, red) * (1.0f / Hh);
    float var = 0.f;
    #pragma unroll
    for (int i = 0; i < 4; i++) { float d = v[i] - mu; var += d * d; }
    float vt = block_sum(var, red) * (1.0f / Hh);
    float inv = rsqrtf(vt + EPSLN);
    #pragma unroll
    for (int i = 0; i < 4; i++) {
        int c = tid + i * 256;
        out[(long)m * Hh + c] = (v[i] - mu) * inv * s[c] + bb[c];
    }
}

// ---------------- residual + LayerNorm: h = LN(h + y) ----------------
__global__ void add_ln_kernel(float* __restrict__ h, const float* __restrict__ y,
                              const float* __restrict__ s, const float* __restrict__ bb) {
    __shared__ float red[256];
    int m = blockIdx.x, tid = threadIdx.x;
    long base = (long)m * Hh;
    float v[4];
    #pragma unroll
    for (int i = 0; i < 4; i++) { int c = tid + i * 256; v[i] = h[base + c] + y[base + c]; }
    float sum = 0.f;
    #pragma unroll
    for (int i = 0; i < 4; i++) sum += v[i];
    float mu = block_sum(sum, red) * (1.0f / Hh);
    float var = 0.f;
    #pragma unroll
    for (int i = 0; i < 4; i++) { float d = v[i] - mu; var += d * d; }
    float vt = block_sum(var, red) * (1.0f / Hh);
    float inv = rsqrtf(vt + EPSLN);
    #pragma unroll
    for (int i = 0; i < 4; i++) {
        int c = tid + i * 256;
        h[base + c] = (v[i] - mu) * inv * s[c] + bb[c];
    }
}

// ---------------- small-N SGEMM (decoder head, N=14) ----------------
#define BM 64
#define BN 64
#define BK 16
__global__ void gemm_bias_kernel(const float* __restrict__ A, const float* __restrict__ W,
                                 const float* __restrict__ bias, float* __restrict__ C,
                                 int M, int N, int K, int act) {
    __shared__ float As[BK][BM];
    __shared__ float Bs[BK][BN];
    int tid = threadIdx.x;
    int tx = tid & 15, ty = tid >> 4;
    int row0 = blockIdx.y * BM, col0 = blockIdx.x * BN;
    float acc[4][4] = {};
    for (int k0 = 0; k0 < K; k0 += BK) {
        #pragma unroll
        for (int i = 0; i < 4; i++) {
            int idx = tid + i * 256;
            int kk = idx >> 6, mm = idx & 63;
            As[kk][mm] = A[(long)(row0 + mm) * K + k0 + kk];
        }
        #pragma unroll
        for (int i = 0; i < 4; i++) {
            int idx = tid + i * 256;
            int kk = idx >> 6, nn = idx & 63;
            int col = col0 + nn;
            Bs[kk][nn] = (col < N) ? W[(long)(k0 + kk) * N + col] : 0.0f;
        }
        __syncthreads();
        #pragma unroll
        for (int kk = 0; kk < BK; kk++) {
            float a[4], b[4];
            #pragma unroll
            for (int i = 0; i < 4; i++) a[i] = As[kk][ty * 4 + i];
            #pragma unroll
            for (int j = 0; j < 4; j++) b[j] = Bs[kk][tx * 4 + j];
            #pragma unroll
            for (int i = 0; i < 4; i++)
                #pragma unroll
                for (int j = 0; j < 4; j++)
                    acc[i][j] += a[i] * b[j];
        }
        __syncthreads();
    }
    #pragma unroll
    for (int i = 0; i < 4; i++) {
        int r = row0 + ty * 4 + i;
        #pragma unroll
        for (int j = 0; j < 4; j++) {
            int c = col0 + tx * 4 + j;
            if (c < N) {
                float v = acc[i][j] + bias[c];
                if (act == 1) v = gelu_exact(v);
                C[(long)r * N + c] = v;
            }
        }
    }
}

// ---------------- batched NN SGEMM (ctx = probs @ v) --------------------
__global__ void bgemm_nn_kernel(const float* __restrict__ Ao, const float* __restrict__ Bo,
                                float* __restrict__ Co,
                                int M, int N, int K, int lda, int ldb, int ldc,
                                long sAb, long sAh, long sBb, long sBh, long sCb, long sCh) {
    int bh = blockIdx.z;
    int b = bh / NHh, h = bh % NHh;
    const float* A  = Ao + b * sAb + h * sAh;
    const float* Bm = Bo + b * sBb + h * sBh;
    float*       C  = Co + b * sCb + h * sCh;
    __shared__ float As[BK][BM];
    __shared__ float Bs[BK][BN];
    int tid = threadIdx.x;
    int tx = tid & 15, ty = tid >> 4;
    int row0 = blockIdx.y * BM, col0 = blockIdx.x * BN;
    float acc[4][4] = {};
    for (int k0 = 0; k0 < K; k0 += BK) {
        #pragma unroll
        for (int i = 0; i < 4; i++) {
            int idx = tid + i * 256;
            int kk = idx >> 6, mm = idx & 63;
            As[kk][mm] = A[(long)(row0 + mm) * lda + k0 + kk];
        }
        #pragma unroll
        for (int i = 0; i < 4; i++) {
            int idx = tid + i * 256;
            int kk = idx >> 6, nn = idx & 63;
            Bs[kk][nn] = Bm[(long)(k0 + kk) * ldb + col0 + nn];
        }
        __syncthreads();
        #pragma unroll
        for (int kk = 0; kk < BK; kk++) {
            float a[4], bq[4];
            #pragma unroll
            for (int i = 0; i < 4; i++) a[i] = As[kk][ty * 4 + i];
            #pragma unroll
            for (int j = 0; j < 4; j++) bq[j] = Bs[kk][tx * 4 + j];
            #pragma unroll
            for (int i = 0; i < 4; i++)
                #pragma unroll
                for (int j = 0; j < 4; j++)
                    acc[i][j] += a[i] * bq[j];
        }
        __syncthreads();
    }
    #pragma unroll
    for (int i = 0; i < 4; i++)
        #pragma unroll
        for (int j = 0; j < 4; j++)
            C[(long)(row0 + ty * 4 + i) * ldc + col0 + tx * 4 + j] = acc[i][j];
}

// ---------------- fused gather + scale + mask + softmax (in place) ----
__global__ void softmax_kernel(float* __restrict__ scores,
                               const float* __restrict__ c2p, const float* __restrict__ p2c,
                               const int* __restrict__ ic2p, const int* __restrict__ ip2c,
                               const int* __restrict__ amask) {
    __shared__ float sm[Ss];
    __shared__ float red[256];
    int q  = blockIdx.x;
    int bh = blockIdx.y;
    int b  = bh / NHh;
    int tid = threadIdx.x;
    const float inv_scale = 0.07216878364870322f;  // 1/sqrt(3*D)
    int maskq = amask[b * Ss + q];
    float* row = scores + ((long)bh * Ss + q) * Ss;
    const float* c2pr = c2p + ((long)bh * Ss + q) * Rr;
    const float* p2cb = p2c + (long)bh * Ss * Rr;

    for (int k = tid; k < Ss; k += 256) {
        float s;
        if (maskq && amask[b * Ss + k]) {
            s = (row[k] + c2pr[ic2p[q * Ss + k]] + p2cb[(long)k * Rr + ip2c[k * Ss + q]]) * inv_scale;
        } else {
            s = -INFINITY;
        }
        sm[k] = s;
    }
    __syncthreads();
    float mx = -INFINITY;
    for (int k = tid; k < Ss; k += 256) mx = fmaxf(mx, sm[k]);
    red[tid] = mx; __syncthreads();
    #pragma unroll
    for (int s = 128; s > 0; s >>= 1) {
        if (tid < s) red[tid] = fmaxf(red[tid], red[tid + s]);
        __syncthreads();
    }
    mx = red[0]; __syncthreads();
    if (mx == -INFINITY) {
        for (int k = tid; k < Ss; k += 256) row[k] = 0.0f;
        return;
    }
    float sum = 0.f;
    for (int k = tid; k < Ss; k += 256) {
        float e = expf(sm[k] - mx);
        sm[k] = e;
        sum += e;
    }
    float tot = block_sum(sum, red);
    float inv = 1.0f / tot;
    for (int k = tid; k < Ss; k += 256) row[k] = sm[k] * inv;
}

// ---------------- loss + output assembly ----------------
__global__ void finalize_kernel(const float* __restrict__ logits, const int* __restrict__ labels,
                                const int* __restrict__ amask, float* __restrict__ out,
                                int out_size) {
    __shared__ float r1[256], r2[256];
    int tid = threadIdx.x;
    float ls = 0.f, ms = 0.f;
    for (int m = tid; m < Mm; m += 256) {
        const float* lr = logits + m * NCc;
        float mx = lr[0];
        #pragma unroll
        for (int c = 1; c < NCc; c++) mx = fmaxf(mx, lr[c]);
        float se = 0.f;
        #pragma unroll
        for (int c = 0; c < NCc; c++) se += expf(lr[c] - mx);
        float lse = logf(se) + mx;
        float nll = lse - lr[labels[m]];
        float mk = amask[m] ? 1.0f : 0.0f;
        ls += nll * mk;
        ms += mk;
    }
    r1[tid] = ls; r2[tid] = ms; __syncthreads();
    #pragma unroll
    for (int s = 128; s > 0; s >>= 1) {
        if (tid < s) { r1[tid] += r1[tid + s]; r2[tid] += r2[tid + s]; }
        __syncthreads();
    }
    float loss = r1[0] / fmaxf(r2[0], 1.0f);
    const int total = Mm * NCc;
    for (int i = tid; i < out_size; i += 256)
        out[i] = (i < total) ? logits[i] : loss;
}

// ---------------- host driver ----------------
extern "C" void kernel_launch(void* const* d_in, const int* in_sizes, int n_in,
                              void* d_out, int out_size) {
    const float* word_emb = (const float*)d_in[0];
    const float* emb_ln_s = (const float*)d_in[1];
    const float* emb_ln_b = (const float*)d_in[2];
    const float* rel_emb  = (const float*)d_in[3];
    const float* rel_ln_s = (const float*)d_in[4];
    const float* rel_ln_b = (const float*)d_in[5];
    const float* Wq = (const float*)d_in[6];
    const float* bq = (const float*)d_in[7];
    const float* Wk = (const float*)d_in[8];
    const float* bk = (const float*)d_in[9];
    const float* Wv = (const float*)d_in[10];
    const float* bv = (const float*)d_in[11];
    const float* Wo = (const float*)d_in[12];
    const float* bo = (const float*)d_in[13];
    const float* ln1_s = (const float*)d_in[14];
    const float* ln1_b = (const float*)d_in[15];
    const float* W1 = (const float*)d_in[16];
    const float* b1 = (const float*)d_in[17];
    const float* W2 = (const float*)d_in[18];
    const float* b2 = (const float*)d_in[19];
    const float* ln2_s = (const float*)d_in[20];
    const float* ln2_b = (const float*)d_in[21];
    const float* Wt = (const float*)d_in[22];
    const float* bt = (const float*)d_in[23];
    const float* tln_s = (const float*)d_in[24];
    const float* tln_b = (const float*)d_in[25];
    const float* Wd = (const float*)d_in[26];
    const float* bd = (const float*)d_in[27];
    const int* input_ids = (const int*)d_in[28];
    const int* amask     = (const int*)d_in[29];
    const int* labels    = (const int*)d_in[30];

    static bool init = false;
    static float *x, *rel, *q, *k, *v, *posk, *posq, *sc, *c2p, *p2c, *ctx, *tmp, *ff, *t, *part, *logits;
    static int *ic2p, *ip2c;
    if (!init) {
        cudaGetSymbolAddress((void**)&x, g_x);
        cudaGetSymbolAddress((void**)&rel, g_rel);
        cudaGetSymbolAddress((void**)&q, g_q);
        cudaGetSymbolAddress((void**)&k, g_k);
        cudaGetSymbolAddress((void**)&v, g_v);
        cudaGetSymbolAddress((void**)&posk, g_posk);
        cudaGetSymbolAddress((void**)&posq, g_posq);
        cudaGetSymbolAddress((void**)&sc, g_sc);
        cudaGetSymbolAddress((void**)&c2p, g_c2p);
        cudaGetSymbolAddress((void**)&p2c, g_p2c);
        cudaGetSymbolAddress((void**)&ctx, g_ctx);
        cudaGetSymbolAddress((void**)&tmp, g_tmp);
        cudaGetSymbolAddress((void**)&ff, g_ff);
        cudaGetSymbolAddress((void**)&t, g_t);
        cudaGetSymbolAddress((void**)&part, g_part);
        cudaGetSymbolAddress((void**)&logits, g_logits);
        cudaGetSymbolAddress((void**)&ic2p, g_ic2p);
        cudaGetSymbolAddress((void**)&ip2c, g_ip2c);
        init = true;
    }

    // precompute
    idx_kernel<<<(Ss * Ss + 255) / 256, 256>>>(ic2p, ip2c);
    ln_kernel<<<Rr, 256>>>(rel_emb, rel, rel_ln_s, rel_ln_b);
    embed_kernel<<<Mm, 256>>>(word_emb, input_ids, amask, emb_ln_s, emb_ln_b, x);

    const long sQKVb = (long)Ss * Hh;
    const long sQKVh = Dd;
    const long sSCb  = (long)NHh * Ss * Ss;
    const long sSCh  = (long)Ss * Ss;

    for (int l = 0; l < Ll; l++) {
        const float* Wq_l = Wq + (long)l * Hh * Hh;  const float* bq_l = bq + l * Hh;
        const float* Wk_l = Wk + (long)l * Hh * Hh;  const float* bk_l = bk + l * Hh;
        const float* Wv_l = Wv + (long)l * Hh * Hh;  const float* bv_l = bv + l * Hh;
        const float* Wo_l = Wo + (long)l * Hh * Hh;  const float* bo_l = bo + l * Hh;
        const float* W1_l = W1 + (long)l * Hh * FFf; const float* b1_l = b1 + l * FFf;
        const float* W2_l = W2 + (long)l * FFf * Hh; const float* b2_l = b2 + l * Hh;

        // q/k/v + pos_k/pos_q in one launch (256 effective blocks)
        qkvpos_kernel<<<dim3(Hh / TBN, Mm / TBM, 5), 256>>>(
            x, rel, Wq_l, Wk_l, Wv_l, bq_l, bk_l, bv_l, q, k, v, posk, posq);

        // scores + c2p + p2c in one NT launch (1536 blocks)
        att_nt128_kernel<<<dim3(4, 4, 96), 256>>>(q, k, posk, posq, sc, c2p, p2c);

        softmax_kernel<<<dim3(Ss, Bb * NHh), 256>>>(sc, c2p, p2c, ic2p, ip2c, amask);

        // ctx[b,q,h,d] = probs @ v
        bgemm_nn_kernel<<<dim3(Dd / BN, Ss / BM, Bb * NHh), 256>>>(
            sc, v, ctx, Ss, Dd, Ss, Ss, Hh, Hh,
            sSCb, sSCh, sQKVb, sQKVh, sQKVb, sQKVh);

        // o-projection: split-K 2
        gemm128_split_kernel<<<dim3(Hh / TBN, Mm / TBM, 2), 256>>>(ctx, Wo_l, part, Hh, Hh, 2);
        reduce_bias_kernel<<<(Mm * Hh + 255) / 256, 256>>>(part, bo_l, tmp, Mm, Hh, 2, 0);
        add_ln_kernel<<<Mm, 256>>>(x, tmp, ln1_s + l * Hh, ln1_b + l * Hh);

        // FFN
        gemm128_kernel<<<dim3(FFf / TBN, Mm / TBM), 256>>>(x, W1_l, b1_l, ff, FFf, Hh, 1);
        gemm128_split_kernel<<<dim3(Hh / TBN, Mm / TBM, 4), 256>>>(ff, W2_l, part, Hh, FFf, 4);
        reduce_bias_kernel<<<(Mm * Hh + 255) / 256, 256>>>(part, b2_l, tmp, Mm, Hh, 4, 0);
        add_ln_kernel<<<Mm, 256>>>(x, tmp, ln2_s + l * Hh, ln2_b + l * Hh);
    }

    // head: transform (GELU) via split-K 2, then LN, then decoder
    gemm128_split_kernel<<<dim3(Hh / TBN, Mm / TBM, 2), 256>>>(x, Wt, part, Hh, Hh, 2);
    reduce_bias_kernel<<<(Mm * Hh + 255) / 256, 256>>>(part, bt, t, Mm, Hh, 2, 1);
    ln_kernel<<<Mm, 256>>>(t, t, tln_s, tln_b);
    gemm_bias_kernel<<<dim3((NCc + BN - 1) / BN, Mm / BM), 256>>>(t, Wd, bd, logits, Mm, NCc, Hh, 0);

    finalize_kernel<<<1, 256>>>(logits, labels, amask, (float*)d_out, out_size);
}

// round 8
// speedup vs baseline: 3.7602x; 2.5106x over previous
#include <cuda_runtime.h>
#include <cuda_bf16.h>
#include <math.h>

// ---------------- problem constants ----------------
#define Bb   2
#define Ss   512
#define Hh   1024
#define NHh  16
#define Dd   64
#define Ll   4
#define FFf  4096
#define Vv   12800
#define NCc  14
#define SPAN 256
#define Rr   512           // 2*SPAN
#define Mm   (Bb*Ss)       // 1024 tokens
#define EPSLN 1e-7f

// ---------------- static device scratch (no allocation allowed) ----------------
__device__ float g_x   [Mm*Hh];
__device__ float g_rel [Rr*Hh];
__device__ float g_q   [Mm*Hh];
__device__ float g_k   [Mm*Hh];
__device__ float g_v   [Mm*Hh];
__device__ float g_posk[Rr*Hh];
__device__ float g_posq[Rr*Hh];
__device__ float g_sc  [(long)Bb*NHh*Ss*Ss];
__device__ float g_c2p [(long)Bb*NHh*Ss*Rr];
__device__ float g_p2c [(long)Bb*NHh*Ss*Rr];
__device__ float g_ctx [Mm*Hh];
__device__ float g_tmp [Mm*Hh];
__device__ float g_ff  [Mm*FFf];
__device__ float g_t   [Mm*Hh];
__device__ float g_part[4L*Mm*Hh];     // split-K partials
__device__ float g_logits[Mm*NCc];
__device__ int   g_ic2p[Ss*Ss];
__device__ int   g_ip2c[Ss*Ss];

// ---------------- helpers ----------------
__device__ __forceinline__ float block_sum(float v, float* red) {
    int tid = threadIdx.x;
    red[tid] = v; __syncthreads();
    #pragma unroll
    for (int s = 128; s > 0; s >>= 1) {
        if (tid < s) red[tid] += red[tid + s];
        __syncthreads();
    }
    float r = red[0]; __syncthreads();
    return r;
}

__device__ __forceinline__ float gelu_exact(float x) {
    return 0.5f * x * (1.0f + erff(x * 0.70710678118654752f));
}

// split fp32 into bf16 hi + bf16 lo (raw bit patterns)
__device__ __forceinline__ void bfsplit(float x, unsigned short& h, unsigned short& l) {
    __nv_bfloat16 bh = __float2bfloat16_rn(x);
    float rem = x - __bfloat162float(bh);
    __nv_bfloat16 bl = __float2bfloat16_rn(rem);
    h = *(unsigned short*)&bh;
    l = *(unsigned short*)&bl;
}

// ================= bf16-split tensor-core NN GEMM (128x128 tile) =================
// C = A[M,K] @ W[K,N]; 8 warps, warp tile 32x64, mma.m16n8k16, 3-pass hi/lo split.
struct SmemMMA {
    unsigned short Ahi[128][40];   // stride 40 bf16 (80B) -> conflict-free frag loads
    unsigned short Alo[128][40];
    unsigned short Bhi[32][136];   // k-major natural, padded
    unsigned short Blo[32][136];
};

__device__ __forceinline__ void mma16816(float* c,
                                         unsigned int a0, unsigned int a1,
                                         unsigned int a2, unsigned int a3,
                                         unsigned int b0, unsigned int b1) {
    asm volatile(
        "mma.sync.aligned.m16n8k16.row.col.f32.bf16.bf16.f32 "
        "{%0,%1,%2,%3},{%4,%5,%6,%7},{%8,%9},{%0,%1,%2,%3};\n"
        : "+f"(c[0]), "+f"(c[1]), "+f"(c[2]), "+f"(c[3])
        : "r"(a0), "r"(a1), "r"(a2), "r"(a3), "r"(b0), "r"(b1));
}

__device__ void mma_nn_core(SmemMMA& sm, const float* __restrict__ A, int lda,
                            const float* __restrict__ W, int N,
                            int kstart, int kend, int row0, int col0, float acc[64]) {
    int tid  = threadIdx.x;
    int lane = tid & 31, warp = tid >> 5;
    int wm = warp & 3, wn = warp >> 2;      // warp grid 4 (m) x 2 (n)
    int gg = lane >> 2, qq = lane & 3;

    for (int k0 = kstart; k0 < kend; k0 += 32) {
        // --- load + split A tile: 128 rows x 32 k ---
        #pragma unroll
        for (int i = 0; i < 4; i++) {
            int idx = i * 256 + tid;
            int m = idx >> 3, kq = (idx & 7) * 4;
            float4 av = *(const float4*)(A + (long)(row0 + m) * lda + k0 + kq);
            unsigned short h0,h1,h2,h3,l0,l1,l2,l3;
            bfsplit(av.x,h0,l0); bfsplit(av.y,h1,l1);
            bfsplit(av.z,h2,l2); bfsplit(av.w,h3,l3);
            *(unsigned int*)&sm.Ahi[m][kq]   = (unsigned int)h0 | ((unsigned int)h1 << 16);
            *(unsigned int*)&sm.Ahi[m][kq+2] = (unsigned int)h2 | ((unsigned int)h3 << 16);
            *(unsigned int*)&sm.Alo[m][kq]   = (unsigned int)l0 | ((unsigned int)l1 << 16);
            *(unsigned int*)&sm.Alo[m][kq+2] = (unsigned int)l2 | ((unsigned int)l3 << 16);
        }
        // --- load + split B tile: 32 k x 128 n (k-major natural) ---
        #pragma unroll
        for (int i = 0; i < 4; i++) {
            int idx = i * 256 + tid;
            int kk = idx >> 5, n4 = (idx & 31) * 4;
            float4 wv = *(const float4*)(W + (long)(k0 + kk) * N + col0 + n4);
            unsigned short h0,h1,h2,h3,l0,l1,l2,l3;
            bfsplit(wv.x,h0,l0); bfsplit(wv.y,h1,l1);
            bfsplit(wv.z,h2,l2); bfsplit(wv.w,h3,l3);
            *(unsigned int*)&sm.Bhi[kk][n4]   = (unsigned int)h0 | ((unsigned int)h1 << 16);
            *(unsigned int*)&sm.Bhi[kk][n4+2] = (unsigned int)h2 | ((unsigned int)h3 << 16);
            *(unsigned int*)&sm.Blo[kk][n4]   = (unsigned int)l0 | ((unsigned int)l1 << 16);
            *(unsigned int*)&sm.Blo[kk][n4+2] = (unsigned int)l2 | ((unsigned int)l3 << 16);
        }
        __syncthreads();

        #pragma unroll
        for (int ks = 0; ks < 32; ks += 16) {
            unsigned int ah[2][4], al[2][4];
            #pragma unroll
            for (int mt = 0; mt < 2; mt++) {
                int r  = wm * 32 + mt * 16 + gg;
                int kc = ks + 2 * qq;
                ah[mt][0] = *(unsigned int*)&sm.Ahi[r    ][kc    ];
                ah[mt][1] = *(unsigned int*)&sm.Ahi[r + 8][kc    ];
                ah[mt][2] = *(unsigned int*)&sm.Ahi[r    ][kc + 8];
                ah[mt][3] = *(unsigned int*)&sm.Ahi[r + 8][kc + 8];
                al[mt][0] = *(unsigned int*)&sm.Alo[r    ][kc    ];
                al[mt][1] = *(unsigned int*)&sm.Alo[r + 8][kc    ];
                al[mt][2] = *(unsigned int*)&sm.Alo[r    ][kc + 8];
                al[mt][3] = *(unsigned int*)&sm.Alo[r + 8][kc + 8];
            }
            #pragma unroll
            for (int nt = 0; nt < 8; nt++) {
                int n  = wn * 64 + nt * 8 + gg;
                int kb = ks + 2 * qq;
                unsigned int bh0 = (unsigned int)sm.Bhi[kb    ][n] | ((unsigned int)sm.Bhi[kb + 1][n] << 16);
                unsigned int bh1 = (unsigned int)sm.Bhi[kb + 8][n] | ((unsigned int)sm.Bhi[kb + 9][n] << 16);
                unsigned int bl0 = (unsigned int)sm.Blo[kb    ][n] | ((unsigned int)sm.Blo[kb + 1][n] << 16);
                unsigned int bl1 = (unsigned int)sm.Blo[kb + 8][n] | ((unsigned int)sm.Blo[kb + 9][n] << 16);
                #pragma unroll
                for (int mt = 0; mt < 2; mt++) {
                    float* c = acc + (mt * 8 + nt) * 4;
                    mma16816(c, ah[mt][0], ah[mt][1], ah[mt][2], ah[mt][3], bh0, bh1);
                    mma16816(c, ah[mt][0], ah[mt][1], ah[mt][2], ah[mt][3], bl0, bl1);
                    mma16816(c, al[mt][0], al[mt][1], al[mt][2], al[mt][3], bh0, bh1);
                }
            }
        }
        __syncthreads();
    }
}

__device__ void mma_epi_bias(float* __restrict__ C, const float* __restrict__ bias,
                             float acc[64], int row0, int col0, int ldc, int act) {
    int tid = threadIdx.x, lane = tid & 31, warp = tid >> 5;
    int wm = warp & 3, wn = warp >> 2;
    int gg = lane >> 2, qq = lane & 3;
    #pragma unroll
    for (int mt = 0; mt < 2; mt++)
        #pragma unroll
        for (int nt = 0; nt < 8; nt++) {
            int row = row0 + wm * 32 + mt * 16 + gg;
            int col = col0 + wn * 64 + nt * 8 + 2 * qq;
            const float* c = acc + (mt * 8 + nt) * 4;
            float2 v0 = { c[0] + bias[col], c[1] + bias[col + 1] };
            float2 v1 = { c[2] + bias[col], c[3] + bias[col + 1] };
            if (act) {
                v0.x = gelu_exact(v0.x); v0.y = gelu_exact(v0.y);
                v1.x = gelu_exact(v1.x); v1.y = gelu_exact(v1.y);
            }
            *(float2*)(C + (long)row * ldc + col)       = v0;
            *(float2*)(C + (long)(row + 8) * ldc + col) = v1;
        }
}

__device__ void mma_epi_raw(float* __restrict__ C, float acc[64],
                            int row0, int col0, int ldc) {
    int tid = threadIdx.x, lane = tid & 31, warp = tid >> 5;
    int wm = warp & 3, wn = warp >> 2;
    int gg = lane >> 2, qq = lane & 3;
    #pragma unroll
    for (int mt = 0; mt < 2; mt++)
        #pragma unroll
        for (int nt = 0; nt < 8; nt++) {
            int row = row0 + wm * 32 + mt * 16 + gg;
            int col = col0 + wn * 64 + nt * 8 + 2 * qq;
            const float* c = acc + (mt * 8 + nt) * 4;
            *(float2*)(C + (long)row * ldc + col)       = make_float2(c[0], c[1]);
            *(float2*)(C + (long)(row + 8) * ldc + col) = make_float2(c[2], c[3]);
        }
}

// fused q/k/v + pos_k/pos_q projections (z=0..4), tensor-core path
__global__ __launch_bounds__(256, 2) void qkvpos_mma(
    const float* __restrict__ x, const float* __restrict__ rel,
    const float* __restrict__ Wq, const float* __restrict__ Wk, const float* __restrict__ Wv,
    const float* __restrict__ bq, const float* __restrict__ bk, const float* __restrict__ bv,
    float* q, float* k, float* v, float* posk, float* posq) {
    __shared__ SmemMMA sm;
    int z = blockIdx.z;
    const float *A, *W, *bias; float* C;
    if (z == 0)      { A = x;   W = Wq; bias = bq; C = q; }
    else if (z == 1) { A = x;   W = Wk; bias = bk; C = k; }
    else if (z == 2) { A = x;   W = Wv; bias = bv; C = v; }
    else if (z == 3) { if (blockIdx.y >= 4) return; A = rel; W = Wk; bias = bk; C = posk; }
    else             { if (blockIdx.y >= 4) return; A = rel; W = Wq; bias = bq; C = posq; }
    int row0 = blockIdx.y * 128, col0 = blockIdx.x * 128;
    float acc[64] = {};
    mma_nn_core(sm, A, Hh, W, Hh, 0, Hh, row0, col0, acc);
    mma_epi_bias(C, bias, acc, row0, col0, Hh, 0);
}

// generic tensor-core NN GEMM with bias (+GELU)
__global__ __launch_bounds__(256, 2) void gemm_mma(
    const float* __restrict__ A, const float* __restrict__ W,
    const float* __restrict__ bias, float* C, int N, int K, int act) {
    __shared__ SmemMMA sm;
    int row0 = blockIdx.y * 128, col0 = blockIdx.x * 128;
    float acc[64] = {};
    mma_nn_core(sm, A, K, W, N, 0, K, row0, col0, acc);
    mma_epi_bias(C, bias, acc, row0, col0, N, act);
}

// split-K tensor-core GEMM into partial buffers (deterministic; z = k-chunk)
__global__ __launch_bounds__(256, 2) void gemm_mma_split(
    const float* __restrict__ A, const float* __restrict__ W,
    float* P, int N, int K, int nsplit) {
    __shared__ SmemMMA sm;
    int z = blockIdx.z;
    int kc = K / nsplit;
    int row0 = blockIdx.y * 128, col0 = blockIdx.x * 128;
    float acc[64] = {};
    mma_nn_core(sm, A, K, W, N, z * kc, (z + 1) * kc, row0, col0, acc);
    int M = gridDim.y * 128;
    mma_epi_raw(P + (long)z * M * N, acc, row0, col0, N);
}

__global__ void reduce_bias_kernel(const float* __restrict__ P, const float* __restrict__ bias,
                                   float* __restrict__ C, int M, int N, int nsplit, int act) {
    int i = blockIdx.x * blockDim.x + threadIdx.x;
    long sz = (long)M * N;
    if (i >= sz) return;
    float s = 0.f;
    for (int p = 0; p < nsplit; p++) s += P[(long)p * sz + i];
    s += bias[i & (N - 1)];            // N is a power of two here (1024)
    if (act) s = gelu_exact(s);
    C[i] = s;
}

// ================= fp32 NT machinery (attention scores; K=64 small) =================
#define TBM 128
#define TBN 128
#define TBK 16
#define ASTR (TBM + 4)
struct SmemNT { float As[2][TBK][ASTR]; float Bs[2][TBK][ASTR]; };

__device__ __forceinline__ void gemm_nt_core(
    SmemNT& sm, const float* __restrict__ A, const float* __restrict__ B,
    int lda, int ldb, int K, int row0, int col0, float acc[8][8]) {
    int tid = threadIdx.x;
    int ar = tid >> 2, ac = (tid & 3) << 2;
    int tx = tid & 15, ty = tid >> 4;
    const float* Ap  = A + (long)(row0 + ar) * lda;
    const float* Ap2 = Ap + 64L * lda;
    const float* Bp  = B + (long)(col0 + ar) * ldb;
    const float* Bp2 = Bp + 64L * ldb;

    float4 pa0 = *(const float4*)(Ap  + ac);
    float4 pa1 = *(const float4*)(Ap2 + ac);
    float4 pb0 = *(const float4*)(Bp  + ac);
    float4 pb1 = *(const float4*)(Bp2 + ac);
    sm.As[0][ac+0][ar] = pa0.x; sm.As[0][ac+1][ar] = pa0.y;
    sm.As[0][ac+2][ar] = pa0.z; sm.As[0][ac+3][ar] = pa0.w;
    sm.As[0][ac+0][ar+64] = pa1.x; sm.As[0][ac+1][ar+64] = pa1.y;
    sm.As[0][ac+2][ar+64] = pa1.z; sm.As[0][ac+3][ar+64] = pa1.w;
    sm.Bs[0][ac+0][ar] = pb0.x; sm.Bs[0][ac+1][ar] = pb0.y;
    sm.Bs[0][ac+2][ar] = pb0.z; sm.Bs[0][ac+3][ar] = pb0.w;
    sm.Bs[0][ac+0][ar+64] = pb1.x; sm.Bs[0][ac+1][ar+64] = pb1.y;
    sm.Bs[0][ac+2][ar+64] = pb1.z; sm.Bs[0][ac+3][ar+64] = pb1.w;
    __syncthreads();

    int buf = 0;
    for (int k0 = 0; k0 < K; k0 += TBK) {
        int kn = k0 + TBK;
        bool more = kn < K;
        if (more) {
            pa0 = *(const float4*)(Ap  + kn + ac);
            pa1 = *(const float4*)(Ap2 + kn + ac);
            pb0 = *(const float4*)(Bp  + kn + ac);
            pb1 = *(const float4*)(Bp2 + kn + ac);
        }
        #pragma unroll
        for (int kk = 0; kk < TBK; kk++) {
            float a[8], b[8];
            *(float4*)&a[0] = *(const float4*)&sm.As[buf][kk][ty * 4];
            *(float4*)&a[4] = *(const float4*)&sm.As[buf][kk][ty * 4 + 64];
            *(float4*)&b[0] = *(const float4*)&sm.Bs[buf][kk][tx * 4];
            *(float4*)&b[4] = *(const float4*)&sm.Bs[buf][kk][tx * 4 + 64];
            #pragma unroll
            for (int i = 0; i < 8; i++)
                #pragma unroll
                for (int j = 0; j < 8; j++)
                    acc[i][j] = fmaf(a[i], b[j], acc[i][j]);
        }
        if (more) {
            int nb = buf ^ 1;
            sm.As[nb][ac+0][ar] = pa0.x; sm.As[nb][ac+1][ar] = pa0.y;
            sm.As[nb][ac+2][ar] = pa0.z; sm.As[nb][ac+3][ar] = pa0.w;
            sm.As[nb][ac+0][ar+64] = pa1.x; sm.As[nb][ac+1][ar+64] = pa1.y;
            sm.As[nb][ac+2][ar+64] = pa1.z; sm.As[nb][ac+3][ar+64] = pa1.w;
            sm.Bs[nb][ac+0][ar] = pb0.x; sm.Bs[nb][ac+1][ar] = pb0.y;
            sm.Bs[nb][ac+2][ar] = pb0.z; sm.Bs[nb][ac+3][ar] = pb0.w;
            sm.Bs[nb][ac+0][ar+64] = pb1.x; sm.Bs[nb][ac+1][ar+64] = pb1.y;
            sm.Bs[nb][ac+2][ar+64] = pb1.z; sm.Bs[nb][ac+3][ar+64] = pb1.w;
        }
        __syncthreads();
        buf ^= 1;
    }
}

__device__ __forceinline__ void epilogue_raw(
    float* __restrict__ C, float acc[8][8], int row0, int col0, int ldc) {
    int tid = threadIdx.x;
    int tx = tid & 15, ty = tid >> 4;
    #pragma unroll
    for (int ih = 0; ih < 2; ih++)
        #pragma unroll
        for (int i = 0; i < 4; i++) {
            int r = row0 + ty * 4 + i + ih * 64;
            #pragma unroll
            for (int jh = 0; jh < 2; jh++) {
                int c = col0 + tx * 4 + jh * 64;
                float4 o;
                o.x = acc[ih*4+i][jh*4+0]; o.y = acc[ih*4+i][jh*4+1];
                o.z = acc[ih*4+i][jh*4+2]; o.w = acc[ih*4+i][jh*4+3];
                *(float4*)(C + (long)r * ldc + c) = o;
            }
        }
}

// fused scores / c2p / p2c NT batched GEMM (z = type*32 + bh)
__global__ __launch_bounds__(256, 2) void att_nt128_kernel(
    const float* __restrict__ q, const float* __restrict__ k,
    const float* __restrict__ posk, const float* __restrict__ posq,
    float* sc, float* c2p, float* p2c) {
    __shared__ SmemNT sm;
    int z = blockIdx.z;
    int type = z >> 5;
    int bh = z & 31;
    int b = bh >> 4, h = bh & 15;
    const float* A = ((type == 2) ? k : q) + (long)b * Ss * Hh + (long)h * Dd;
    const float* B;
    if (type == 0)      B = k    + (long)b * Ss * Hh + (long)h * Dd;
    else if (type == 1) B = posk + (long)h * Dd;
    else                B = posq + (long)h * Dd;
    float* C = (type == 0 ? sc : (type == 1 ? c2p : p2c)) + (long)bh * Ss * 512;
    int row0 = blockIdx.y * TBM, col0 = blockIdx.x * TBN;
    float acc[8][8] = {};
    gemm_nt_core(sm, A, B, Hh, Hh, Dd, row0, col0, acc);
    epilogue_raw(C, acc, row0, col0, 512);
}

// ---------------- relative-position bucket indices ----------------
__global__ void idx_kernel(int* c2pidx, int* p2cidx) {
    int t = blockIdx.x * blockDim.x + threadIdx.x;
    if (t >= Ss * Ss) return;
    int q = t / Ss, k = t % Ss;
    int rel = q - k;
    const int mid = 128;
    int ap = (rel < mid && rel > -mid) ? (mid - 1) : (rel < 0 ? -rel : rel);
    int bucket;
    if (ap <= mid) {
        bucket = rel;
    } else {
        const float divisor = (float)1.3843393288235763;  // np.log(511/128) as f32
        float lp = ceilf(logf((float)ap / 128.0f) / divisor * 127.0f) + 128.0f;
        float sgn = (rel > 0) ? 1.0f : ((rel < 0) ? -1.0f : 0.0f);
        bucket = (int)(lp * sgn);
    }
    int c = bucket + SPAN;  c = c < 0 ? 0 : (c > 2 * SPAN - 1 ? 2 * SPAN - 1 : c);
    int p = -bucket + SPAN; p = p < 0 ? 0 : (p > 2 * SPAN - 1 ? 2 * SPAN - 1 : p);
    c2pidx[t] = c;
    p2cidx[t] = p;
}

// ---------------- embedding: x = LN(word_emb[ids]) * mask ----------------
__global__ void embed_kernel(const float* __restrict__ wemb, const int* __restrict__ ids,
                             const int* __restrict__ amask,
                             const float* __restrict__ s, const float* __restrict__ bb,
                             float* __restrict__ out) {
    __shared__ float red[256];
    int m = blockIdx.x, tid = threadIdx.x;
    const float* in = wemb + (long)ids[m] * Hh;
    float v[4];
    #pragma unroll
    for (int i = 0; i < 4; i++) v[i] = in[tid + i * 256];
    float sum = 0.f;
    #pragma unroll
    for (int i = 0; i < 4; i++) sum += v[i];
    float mu = block_sum(sum, red) * (1.0f / Hh);
    float var = 0.f;
    #pragma unroll
    for (int i = 0; i < 4; i++) { float d = v[i] - mu; var += d * d; }
    float vt = block_sum(var, red) * (1.0f / Hh);
    float inv = rsqrtf(vt + EPSLN);
    float mk = amask[m] ? 1.0f : 0.0f;
    #pragma unroll
    for (int i = 0; i < 4; i++) {
        int c = tid + i * 256;
        out[(long)m * Hh + c] = ((v[i] - mu) * inv * s[c] + bb[c]) * mk;
    }
}

// ---------------- plain row LayerNorm over H=1024 ----------------
__global__ void ln_kernel(const float* __restrict__ in, float* __restrict__ out,
                          const float* __restrict__ s, const float* __restrict__ bb) {
    __shared__ float red[256];
    int m = blockIdx.x, tid = threadIdx.x;
    const float* ir = in + (long)m * Hh;
    float v[4];
    #pragma unroll
    for (int i = 0; i < 4; i++) v[i] = ir[tid + i * 256];
    float sum = 0.f;
    #pragma unroll
    for (int i = 0; i < 4; i++) sum += v[i];
    float mu = block_sum(sum, red) * (1.0f / Hh);
    float var = 0.f;
    #pragma unroll
    for (int i = 0; i < 4; i++) { float d = v[i] - mu; var += d * d; }
    float vt = block_sum(var, red) * (1.0f / Hh);
    float inv = rsqrtf(vt + EPSLN);
    #pragma unroll
    for (int i = 0; i < 4; i++) {
        int c = tid + i * 256;
        out[(long)m * Hh + c] = (v[i] - mu) * inv * s[c] + bb[c];
    }
}

// ---------------- residual + LayerNorm: h = LN(h + y) ----------------
__global__ void add_ln_kernel(float* __restrict__ h, const float* __restrict__ y,
                              const float* __restrict__ s, const float* __restrict__ bb) {
    __shared__ float red[256];
    int m = blockIdx.x, tid = threadIdx.x;
    long base = (long)m * Hh;
    float v[4];
    #pragma unroll
    for (int i = 0; i < 4; i++) { int c = tid + i * 256; v[i] = h[base + c] + y[base + c]; }
    float sum = 0.f;
    #pragma unroll
    for (int i = 0; i < 4; i++) sum += v[i];
    float mu = block_sum(sum, red) * (1.0f / Hh);
    float var = 0.f;
    #pragma unroll
    for (int i = 0; i < 4; i++) { float d = v[i] - mu; var += d * d; }
    float vt = block_sum(var, red) * (1.0f / Hh);
    float inv = rsqrtf(vt + EPSLN);
    #pragma unroll
    for (int i = 0; i < 4; i++) {
        int c = tid + i * 256;
        h[base + c] = (v[i] - mu) * inv * s[c] + bb[c];
    }
}

// ---------------- small-N SGEMM (decoder head, N=14) ----------------
#define BM 64
#define BN 64
#define BK 16
__global__ void gemm_bias_kernel(const float* __restrict__ A, const float* __restrict__ W,
                                 const float* __restrict__ bias, float* __restrict__ C,
                                 int M, int N, int K, int act) {
    __shared__ float As[BK][BM];
    __shared__ float Bs[BK][BN];
    int tid = threadIdx.x;
    int tx = tid & 15, ty = tid >> 4;
    int row0 = blockIdx.y * BM, col0 = blockIdx.x * BN;
    float acc[4][4] = {};
    for (int k0 = 0; k0 < K; k0 += BK) {
        #pragma unroll
        for (int i = 0; i < 4; i++) {
            int idx = tid + i * 256;
            int kk = idx >> 6, mm = idx & 63;
            As[kk][mm] = A[(long)(row0 + mm) * K + k0 + kk];
        }
        #pragma unroll
        for (int i = 0; i < 4; i++) {
            int idx = tid + i * 256;
            int kk = idx >> 6, nn = idx & 63;
            int col = col0 + nn;
            Bs[kk][nn] = (col < N) ? W[(long)(k0 + kk) * N + col] : 0.0f;
        }
        __syncthreads();
        #pragma unroll
        for (int kk = 0; kk < BK; kk++) {
            float a[4], b[4];
            #pragma unroll
            for (int i = 0; i < 4; i++) a[i] = As[kk][ty * 4 + i];
            #pragma unroll
            for (int j = 0; j < 4; j++) b[j] = Bs[kk][tx * 4 + j];
            #pragma unroll
            for (int i = 0; i < 4; i++)
                #pragma unroll
                for (int j = 0; j < 4; j++)
                    acc[i][j] += a[i] * b[j];
        }
        __syncthreads();
    }
    #pragma unroll
    for (int i = 0; i < 4; i++) {
        int r = row0 + ty * 4 + i;
        #pragma unroll
        for (int j = 0; j < 4; j++) {
            int c = col0 + tx * 4 + j;
            if (c < N) {
                float v = acc[i][j] + bias[c];
                if (act == 1) v = gelu_exact(v);
                C[(long)r * N + c] = v;
            }
        }
    }
}

// ---------------- batched NN SGEMM (ctx = probs @ v) --------------------
__global__ void bgemm_nn_kernel(const float* __restrict__ Ao, const float* __restrict__ Bo,
                                float* __restrict__ Co,
                                int M, int N, int K, int lda, int ldb, int ldc,
                                long sAb, long sAh, long sBb, long sBh, long sCb, long sCh) {
    int bh = blockIdx.z;
    int b = bh / NHh, h = bh % NHh;
    const float* A  = Ao + b * sAb + h * sAh;
    const float* Bm = Bo + b * sBb + h * sBh;
    float*       C  = Co + b * sCb + h * sCh;
    __shared__ float As[BK][BM];
    __shared__ float Bs[BK][BN];
    int tid = threadIdx.x;
    int tx = tid & 15, ty = tid >> 4;
    int row0 = blockIdx.y * BM, col0 = blockIdx.x * BN;
    float acc[4][4] = {};
    for (int k0 = 0; k0 < K; k0 += BK) {
        #pragma unroll
        for (int i = 0; i < 4; i++) {
            int idx = tid + i * 256;
            int kk = idx >> 6, mm = idx & 63;
            As[kk][mm] = A[(long)(row0 + mm) * lda + k0 + kk];
        }
        #pragma unroll
        for (int i = 0; i < 4; i++) {
            int idx = tid + i * 256;
            int kk = idx >> 6, nn = idx & 63;
            Bs[kk][nn] = Bm[(long)(k0 + kk) * ldb + col0 + nn];
        }
        __syncthreads();
        #pragma unroll
        for (int kk = 0; kk < BK; kk++) {
            float a[4], bq[4];
            #pragma unroll
            for (int i = 0; i < 4; i++) a[i] = As[kk][ty * 4 + i];
            #pragma unroll
            for (int j = 0; j < 4; j++) bq[j] = Bs[kk][tx * 4 + j];
            #pragma unroll
            for (int i = 0; i < 4; i++)
                #pragma unroll
                for (int j = 0; j < 4; j++)
                    acc[i][j] += a[i] * bq[j];
        }
        __syncthreads();
    }
    #pragma unroll
    for (int i = 0; i < 4; i++)
        #pragma unroll
        for (int j = 0; j < 4; j++)
            C[(long)(row0 + ty * 4 + i) * ldc + col0 + tx * 4 + j] = acc[i][j];
}

// ---------------- fused gather + scale + mask + softmax (in place) ----
__global__ void softmax_kernel(float* __restrict__ scores,
                               const float* __restrict__ c2p, const float* __restrict__ p2c,
                               const int* __restrict__ ic2p, const int* __restrict__ ip2c,
                               const int* __restrict__ amask) {
    __shared__ float sm[Ss];
    __shared__ float red[256];
    int q  = blockIdx.x;
    int bh = blockIdx.y;
    int b  = bh / NHh;
    int tid = threadIdx.x;
    const float inv_scale = 0.07216878364870322f;  // 1/sqrt(3*D)
    int maskq = amask[b * Ss + q];
    float* row = scores + ((long)bh * Ss + q) * Ss;
    const float* c2pr = c2p + ((long)bh * Ss + q) * Rr;
    const float* p2cb = p2c + (long)bh * Ss * Rr;

    for (int k = tid; k < Ss; k += 256) {
        float s;
        if (maskq && amask[b * Ss + k]) {
            s = (row[k] + c2pr[ic2p[q * Ss + k]] + p2cb[(long)k * Rr + ip2c[k * Ss + q]]) * inv_scale;
        } else {
            s = -INFINITY;
        }
        sm[k] = s;
    }
    __syncthreads();
    float mx = -INFINITY;
    for (int k = tid; k < Ss; k += 256) mx = fmaxf(mx, sm[k]);
    red[tid] = mx; __syncthreads();
    #pragma unroll
    for (int s = 128; s > 0; s >>= 1) {
        if (tid < s) red[tid] = fmaxf(red[tid], red[tid + s]);
        __syncthreads();
    }
    mx = red[0]; __syncthreads();
    if (mx == -INFINITY) {
        for (int k = tid; k < Ss; k += 256) row[k] = 0.0f;
        return;
    }
    float sum = 0.f;
    for (int k = tid; k < Ss; k += 256) {
        float e = expf(sm[k] - mx);
        sm[k] = e;
        sum += e;
    }
    float tot = block_sum(sum, red);
    float inv = 1.0f / tot;
    for (int k = tid; k < Ss; k += 256) row[k] = sm[k] * inv;
}

// ---------------- loss + output assembly ----------------
__global__ void finalize_kernel(const float* __restrict__ logits, const int* __restrict__ labels,
                                const int* __restrict__ amask, float* __restrict__ out,
                                int out_size) {
    __shared__ float r1[256], r2[256];
    int tid = threadIdx.x;
    float ls = 0.f, ms = 0.f;
    for (int m = tid; m < Mm; m += 256) {
        const float* lr = logits + m * NCc;
        float mx = lr[0];
        #pragma unroll
        for (int c = 1; c < NCc; c++) mx = fmaxf(mx, lr[c]);
        float se = 0.f;
        #pragma unroll
        for (int c = 0; c < NCc; c++) se += expf(lr[c] - mx);
        float lse = logf(se) + mx;
        float nll = lse - lr[labels[m]];
        float mk = amask[m] ? 1.0f : 0.0f;
        ls += nll * mk;
        ms += mk;
    }
    r1[tid] = ls; r2[tid] = ms; __syncthreads();
    #pragma unroll
    for (int s = 128; s > 0; s >>= 1) {
        if (tid < s) { r1[tid] += r1[tid + s]; r2[tid] += r2[tid + s]; }
        __syncthreads();
    }
    float loss = r1[0] / fmaxf(r2[0], 1.0f);
    const int total = Mm * NCc;
    for (int i = tid; i < out_size; i += 256)
        out[i] = (i < total) ? logits[i] : loss;
}

// ---------------- host driver ----------------
extern "C" void kernel_launch(void* const* d_in, const int* in_sizes, int n_in,
                              void* d_out, int out_size) {
    const float* word_emb = (const float*)d_in[0];
    const float* emb_ln_s = (const float*)d_in[1];
    const float* emb_ln_b = (const float*)d_in[2];
    const float* rel_emb  = (const float*)d_in[3];
    const float* rel_ln_s = (const float*)d_in[4];
    const float* rel_ln_b = (const float*)d_in[5];
    const float* Wq = (const float*)d_in[6];
    const float* bq = (const float*)d_in[7];
    const float* Wk = (const float*)d_in[8];
    const float* bk = (const float*)d_in[9];
    const float* Wv = (const float*)d_in[10];
    const float* bv = (const float*)d_in[11];
    const float* Wo = (const float*)d_in[12];
    const float* bo = (const float*)d_in[13];
    const float* ln1_s = (const float*)d_in[14];
    const float* ln1_b = (const float*)d_in[15];
    const float* W1 = (const float*)d_in[16];
    const float* b1 = (const float*)d_in[17];
    const float* W2 = (const float*)d_in[18];
    const float* b2 = (const float*)d_in[19];
    const float* ln2_s = (const float*)d_in[20];
    const float* ln2_b = (const float*)d_in[21];
    const float* Wt = (const float*)d_in[22];
    const float* bt = (const float*)d_in[23];
    const float* tln_s = (const float*)d_in[24];
    const float* tln_b = (const float*)d_in[25];
    const float* Wd = (const float*)d_in[26];
    const float* bd = (const float*)d_in[27];
    const int* input_ids = (const int*)d_in[28];
    const int* amask     = (const int*)d_in[29];
    const int* labels    = (const int*)d_in[30];

    static bool init = false;
    static float *x, *rel, *q, *k, *v, *posk, *posq, *sc, *c2p, *p2c, *ctx, *tmp, *ff, *t, *part, *logits;
    static int *ic2p, *ip2c;
    if (!init) {
        cudaGetSymbolAddress((void**)&x, g_x);
        cudaGetSymbolAddress((void**)&rel, g_rel);
        cudaGetSymbolAddress((void**)&q, g_q);
        cudaGetSymbolAddress((void**)&k, g_k);
        cudaGetSymbolAddress((void**)&v, g_v);
        cudaGetSymbolAddress((void**)&posk, g_posk);
        cudaGetSymbolAddress((void**)&posq, g_posq);
        cudaGetSymbolAddress((void**)&sc, g_sc);
        cudaGetSymbolAddress((void**)&c2p, g_c2p);
        cudaGetSymbolAddress((void**)&p2c, g_p2c);
        cudaGetSymbolAddress((void**)&ctx, g_ctx);
        cudaGetSymbolAddress((void**)&tmp, g_tmp);
        cudaGetSymbolAddress((void**)&ff, g_ff);
        cudaGetSymbolAddress((void**)&t, g_t);
        cudaGetSymbolAddress((void**)&part, g_part);
        cudaGetSymbolAddress((void**)&logits, g_logits);
        cudaGetSymbolAddress((void**)&ic2p, g_ic2p);
        cudaGetSymbolAddress((void**)&ip2c, g_ip2c);
        init = true;
    }

    // precompute
    idx_kernel<<<(Ss * Ss + 255) / 256, 256>>>(ic2p, ip2c);
    ln_kernel<<<Rr, 256>>>(rel_emb, rel, rel_ln_s, rel_ln_b);
    embed_kernel<<<Mm, 256>>>(word_emb, input_ids, amask, emb_ln_s, emb_ln_b, x);

    const long sQKVb = (long)Ss * Hh;
    const long sQKVh = Dd;
    const long sSCb  = (long)NHh * Ss * Ss;
    const long sSCh  = (long)Ss * Ss;

    for (int l = 0; l < Ll; l++) {
        const float* Wq_l = Wq + (long)l * Hh * Hh;  const float* bq_l = bq + l * Hh;
        const float* Wk_l = Wk + (long)l * Hh * Hh;  const float* bk_l = bk + l * Hh;
        const float* Wv_l = Wv + (long)l * Hh * Hh;  const float* bv_l = bv + l * Hh;
        const float* Wo_l = Wo + (long)l * Hh * Hh;  const float* bo_l = bo + l * Hh;
        const float* W1_l = W1 + (long)l * Hh * FFf; const float* b1_l = b1 + l * FFf;
        const float* W2_l = W2 + (long)l * FFf * Hh; const float* b2_l = b2 + l * Hh;

        // q/k/v + pos_k/pos_q on tensor cores (one launch)
        qkvpos_mma<<<dim3(8, 8, 5), 256>>>(
            x, rel, Wq_l, Wk_l, Wv_l, bq_l, bk_l, bv_l, q, k, v, posk, posq);

        // scores + c2p + p2c in one NT launch (1536 blocks)
        att_nt128_kernel<<<dim3(4, 4, 96), 256>>>(q, k, posk, posq, sc, c2p, p2c);

        softmax_kernel<<<dim3(Ss, Bb * NHh), 256>>>(sc, c2p, p2c, ic2p, ip2c, amask);

        // ctx[b,q,h,d] = probs @ v
        bgemm_nn_kernel<<<dim3(Dd / BN, Ss / BM, Bb * NHh), 256>>>(
            sc, v, ctx, Ss, Dd, Ss, Ss, Hh, Hh,
            sSCb, sSCh, sQKVb, sQKVh, sQKVb, sQKVh);

        // o-projection on tensor cores: split-K 4
        gemm_mma_split<<<dim3(8, 8, 4), 256>>>(ctx, Wo_l, part, Hh, Hh, 4);
        reduce_bias_kernel<<<(Mm * Hh + 255) / 256, 256>>>(part, bo_l, tmp, Mm, Hh, 4, 0);
        add_ln_kernel<<<Mm, 256>>>(x, tmp, ln1_s + l * Hh, ln1_b + l * Hh);

        // FFN on tensor cores
        gemm_mma<<<dim3(32, 8), 256>>>(x, W1_l, b1_l, ff, FFf, Hh, 1);
        gemm_mma_split<<<dim3(8, 8, 4), 256>>>(ff, W2_l, part, Hh, FFf, 4);
        reduce_bias_kernel<<<(Mm * Hh + 255) / 256, 256>>>(part, b2_l, tmp, Mm, Hh, 4, 0);
        add_ln_kernel<<<Mm, 256>>>(x, tmp, ln2_s + l * Hh, ln2_b + l * Hh);
    }

    // head: transform (GELU) on tensor cores via split-K 4, then LN, then decoder
    gemm_mma_split<<<dim3(8, 8, 4), 256>>>(x, Wt, part, Hh, Hh, 4);
    reduce_bias_kernel<<<(Mm * Hh + 255) / 256, 256>>>(part, bt, t, Mm, Hh, 4, 1);
    ln_kernel<<<Mm, 256>>>(t, t, tln_s, tln_b);
    gemm_bias_kernel<<<dim3((NCc + BN - 1) / BN, Mm / BM), 256>>>(t, Wd, bd, logits, Mm, NCc, Hh, 0);

    finalize_kernel<<<1, 256>>>(logits, labels, amask, (float*)d_out, out_size);
}

// round 9
// speedup vs baseline: 4.2370x; 1.1268x over previous
#include <cuda_runtime.h>
#include <cuda_bf16.h>
#include <math.h>

// ---------------- problem constants ----------------
#define Bb   2
#define Ss   512
#define Hh   1024
#define NHh  16
#define Dd   64
#define Ll   4
#define FFf  4096
#define Vv   12800
#define NCc  14
#define SPAN 256
#define Rr   512           // 2*SPAN
#define Mm   (Bb*Ss)       // 1024 tokens
#define EPSLN 1e-7f

// ---------------- static device scratch (no allocation allowed) ----------------
__device__ float g_x   [Mm*Hh];
__device__ float g_rel [Rr*Hh];
__device__ float g_q   [Mm*Hh];
__device__ float g_k   [Mm*Hh];
__device__ float g_v   [Mm*Hh];
__device__ float g_posk[Rr*Hh];
__device__ float g_posq[Rr*Hh];
__device__ float g_sc  [(long)Bb*NHh*Ss*Ss];
__device__ float g_c2p [(long)Bb*NHh*Ss*Rr];
__device__ float g_p2c [(long)Bb*NHh*Ss*Rr];
__device__ float g_ctx [Mm*Hh];
__device__ float g_tmp [Mm*Hh];
__device__ float g_ff  [Mm*FFf];
__device__ float g_t   [Mm*Hh];
__device__ float g_part[4L*Mm*Hh];     // split-K partials
__device__ float g_logits[Mm*NCc];
__device__ int   g_ic2p[Ss*Ss];
__device__ int   g_ip2c[Ss*Ss];

// ---------------- helpers ----------------
__device__ __forceinline__ float block_sum(float v, float* red) {
    int tid = threadIdx.x;
    red[tid] = v; __syncthreads();
    #pragma unroll
    for (int s = 128; s > 0; s >>= 1) {
        if (tid < s) red[tid] += red[tid + s];
        __syncthreads();
    }
    float r = red[0]; __syncthreads();
    return r;
}

__device__ __forceinline__ float gelu_exact(float x) {
    return 0.5f * x * (1.0f + erff(x * 0.70710678118654752f));
}

// split fp32 into bf16 hi + bf16 lo (raw bit patterns)
__device__ __forceinline__ void bfsplit(float x, unsigned short& h, unsigned short& l) {
    __nv_bfloat16 bh = __float2bfloat16_rn(x);
    float rem = x - __bfloat162float(bh);
    __nv_bfloat16 bl = __float2bfloat16_rn(rem);
    h = *(unsigned short*)&bh;
    l = *(unsigned short*)&bl;
}

__device__ __forceinline__ void mma16816(float* c,
                                         unsigned int a0, unsigned int a1,
                                         unsigned int a2, unsigned int a3,
                                         unsigned int b0, unsigned int b1) {
    asm volatile(
        "mma.sync.aligned.m16n8k16.row.col.f32.bf16.bf16.f32 "
        "{%0,%1,%2,%3},{%4,%5,%6,%7},{%8,%9},{%0,%1,%2,%3};\n"
        : "+f"(c[0]), "+f"(c[1]), "+f"(c[2]), "+f"(c[3])
        : "r"(a0), "r"(a1), "r"(a2), "r"(a3), "r"(b0), "r"(b1));
}

// ================= bf16-split tensor-core NN GEMM (128x128 tile) =================
// C = A[M,K] @ W[K,N]; 8 warps, warp tile 32x64, mma.m16n8k16, 3-pass hi/lo split.
struct SmemMMA {
    unsigned short Ahi[128][40];   // stride 40 bf16 (80B) -> conflict-free frag loads
    unsigned short Alo[128][40];
    unsigned short Bhi[32][136];   // k-major natural, padded
    unsigned short Blo[32][136];
};

__device__ void mma_nn_core(SmemMMA& sm, const float* __restrict__ A, int lda,
                            const float* __restrict__ W, int N,
                            int kstart, int kend, int row0, int col0, float acc[64]) {
    int tid  = threadIdx.x;
    int lane = tid & 31, warp = tid >> 5;
    int wm = warp & 3, wn = warp >> 2;      // warp grid 4 (m) x 2 (n)
    int gg = lane >> 2, qq = lane & 3;

    for (int k0 = kstart; k0 < kend; k0 += 32) {
        // --- load + split A tile: 128 rows x 32 k ---
        #pragma unroll
        for (int i = 0; i < 4; i++) {
            int idx = i * 256 + tid;
            int m = idx >> 3, kq = (idx & 7) * 4;
            float4 av = *(const float4*)(A + (long)(row0 + m) * lda + k0 + kq);
            unsigned short h0,h1,h2,h3,l0,l1,l2,l3;
            bfsplit(av.x,h0,l0); bfsplit(av.y,h1,l1);
            bfsplit(av.z,h2,l2); bfsplit(av.w,h3,l3);
            *(unsigned int*)&sm.Ahi[m][kq]   = (unsigned int)h0 | ((unsigned int)h1 << 16);
            *(unsigned int*)&sm.Ahi[m][kq+2] = (unsigned int)h2 | ((unsigned int)h3 << 16);
            *(unsigned int*)&sm.Alo[m][kq]   = (unsigned int)l0 | ((unsigned int)l1 << 16);
            *(unsigned int*)&sm.Alo[m][kq+2] = (unsigned int)l2 | ((unsigned int)l3 << 16);
        }
        // --- load + split B tile: 32 k x 128 n (k-major natural) ---
        #pragma unroll
        for (int i = 0; i < 4; i++) {
            int idx = i * 256 + tid;
            int kk = idx >> 5, n4 = (idx & 31) * 4;
            float4 wv = *(const float4*)(W + (long)(k0 + kk) * N + col0 + n4);
            unsigned short h0,h1,h2,h3,l0,l1,l2,l3;
            bfsplit(wv.x,h0,l0); bfsplit(wv.y,h1,l1);
            bfsplit(wv.z,h2,l2); bfsplit(wv.w,h3,l3);
            *(unsigned int*)&sm.Bhi[kk][n4]   = (unsigned int)h0 | ((unsigned int)h1 << 16);
            *(unsigned int*)&sm.Bhi[kk][n4+2] = (unsigned int)h2 | ((unsigned int)h3 << 16);
            *(unsigned int*)&sm.Blo[kk][n4]   = (unsigned int)l0 | ((unsigned int)l1 << 16);
            *(unsigned int*)&sm.Blo[kk][n4+2] = (unsigned int)l2 | ((unsigned int)l3 << 16);
        }
        __syncthreads();

        #pragma unroll
        for (int ks = 0; ks < 32; ks += 16) {
            unsigned int ah[2][4], al[2][4];
            #pragma unroll
            for (int mt = 0; mt < 2; mt++) {
                int r  = wm * 32 + mt * 16 + gg;
                int kc = ks + 2 * qq;
                ah[mt][0] = *(unsigned int*)&sm.Ahi[r    ][kc    ];
                ah[mt][1] = *(unsigned int*)&sm.Ahi[r + 8][kc    ];
                ah[mt][2] = *(unsigned int*)&sm.Ahi[r    ][kc + 8];
                ah[mt][3] = *(unsigned int*)&sm.Ahi[r + 8][kc + 8];
                al[mt][0] = *(unsigned int*)&sm.Alo[r    ][kc    ];
                al[mt][1] = *(unsigned int*)&sm.Alo[r + 8][kc    ];
                al[mt][2] = *(unsigned int*)&sm.Alo[r    ][kc + 8];
                al[mt][3] = *(unsigned int*)&sm.Alo[r + 8][kc + 8];
            }
            #pragma unroll
            for (int nt = 0; nt < 8; nt++) {
                int n  = wn * 64 + nt * 8 + gg;
                int kb = ks + 2 * qq;
                unsigned int bh0 = (unsigned int)sm.Bhi[kb    ][n] | ((unsigned int)sm.Bhi[kb + 1][n] << 16);
                unsigned int bh1 = (unsigned int)sm.Bhi[kb + 8][n] | ((unsigned int)sm.Bhi[kb + 9][n] << 16);
                unsigned int bl0 = (unsigned int)sm.Blo[kb    ][n] | ((unsigned int)sm.Blo[kb + 1][n] << 16);
                unsigned int bl1 = (unsigned int)sm.Blo[kb + 8][n] | ((unsigned int)sm.Blo[kb + 9][n] << 16);
                #pragma unroll
                for (int mt = 0; mt < 2; mt++) {
                    float* c = acc + (mt * 8 + nt) * 4;
                    mma16816(c, ah[mt][0], ah[mt][1], ah[mt][2], ah[mt][3], bh0, bh1);
                    mma16816(c, ah[mt][0], ah[mt][1], ah[mt][2], ah[mt][3], bl0, bl1);
                    mma16816(c, al[mt][0], al[mt][1], al[mt][2], al[mt][3], bh0, bh1);
                }
            }
        }
        __syncthreads();
    }
}

__device__ void mma_epi_bias(float* __restrict__ C, const float* __restrict__ bias,
                             float acc[64], int row0, int col0, int ldc, int act) {
    int tid = threadIdx.x, lane = tid & 31, warp = tid >> 5;
    int wm = warp & 3, wn = warp >> 2;
    int gg = lane >> 2, qq = lane & 3;
    #pragma unroll
    for (int mt = 0; mt < 2; mt++)
        #pragma unroll
        for (int nt = 0; nt < 8; nt++) {
            int row = row0 + wm * 32 + mt * 16 + gg;
            int col = col0 + wn * 64 + nt * 8 + 2 * qq;
            const float* c = acc + (mt * 8 + nt) * 4;
            float2 v0 = { c[0] + bias[col], c[1] + bias[col + 1] };
            float2 v1 = { c[2] + bias[col], c[3] + bias[col + 1] };
            if (act) {
                v0.x = gelu_exact(v0.x); v0.y = gelu_exact(v0.y);
                v1.x = gelu_exact(v1.x); v1.y = gelu_exact(v1.y);
            }
            *(float2*)(C + (long)row * ldc + col)       = v0;
            *(float2*)(C + (long)(row + 8) * ldc + col) = v1;
        }
}

__device__ void mma_epi_raw(float* __restrict__ C, float acc[64],
                            int row0, int col0, int ldc) {
    int tid = threadIdx.x, lane = tid & 31, warp = tid >> 5;
    int wm = warp & 3, wn = warp >> 2;
    int gg = lane >> 2, qq = lane & 3;
    #pragma unroll
    for (int mt = 0; mt < 2; mt++)
        #pragma unroll
        for (int nt = 0; nt < 8; nt++) {
            int row = row0 + wm * 32 + mt * 16 + gg;
            int col = col0 + wn * 64 + nt * 8 + 2 * qq;
            const float* c = acc + (mt * 8 + nt) * 4;
            *(float2*)(C + (long)row * ldc + col)       = make_float2(c[0], c[1]);
            *(float2*)(C + (long)(row + 8) * ldc + col) = make_float2(c[2], c[3]);
        }
}

// fused q/k/v + pos_k/pos_q projections (z=0..4), tensor-core path
__global__ __launch_bounds__(256, 2) void qkvpos_mma(
    const float* __restrict__ x, const float* __restrict__ rel,
    const float* __restrict__ Wq, const float* __restrict__ Wk, const float* __restrict__ Wv,
    const float* __restrict__ bq, const float* __restrict__ bk, const float* __restrict__ bv,
    float* q, float* k, float* v, float* posk, float* posq) {
    __shared__ SmemMMA sm;
    int z = blockIdx.z;
    const float *A, *W, *bias; float* C;
    if (z == 0)      { A = x;   W = Wq; bias = bq; C = q; }
    else if (z == 1) { A = x;   W = Wk; bias = bk; C = k; }
    else if (z == 2) { A = x;   W = Wv; bias = bv; C = v; }
    else if (z == 3) { if (blockIdx.y >= 4) return; A = rel; W = Wk; bias = bk; C = posk; }
    else             { if (blockIdx.y >= 4) return; A = rel; W = Wq; bias = bq; C = posq; }
    int row0 = blockIdx.y * 128, col0 = blockIdx.x * 128;
    float acc[64] = {};
    mma_nn_core(sm, A, Hh, W, Hh, 0, Hh, row0, col0, acc);
    mma_epi_bias(C, bias, acc, row0, col0, Hh, 0);
}

// generic tensor-core NN GEMM with bias (+GELU)
__global__ __launch_bounds__(256, 2) void gemm_mma(
    const float* __restrict__ A, const float* __restrict__ W,
    const float* __restrict__ bias, float* C, int N, int K, int act) {
    __shared__ SmemMMA sm;
    int row0 = blockIdx.y * 128, col0 = blockIdx.x * 128;
    float acc[64] = {};
    mma_nn_core(sm, A, K, W, N, 0, K, row0, col0, acc);
    mma_epi_bias(C, bias, acc, row0, col0, N, act);
}

// split-K tensor-core GEMM into partial buffers (deterministic; z = k-chunk)
__global__ __launch_bounds__(256, 2) void gemm_mma_split(
    const float* __restrict__ A, const float* __restrict__ W,
    float* P, int N, int K, int nsplit) {
    __shared__ SmemMMA sm;
    int z = blockIdx.z;
    int kc = K / nsplit;
    int row0 = blockIdx.y * 128, col0 = blockIdx.x * 128;
    float acc[64] = {};
    mma_nn_core(sm, A, K, W, N, z * kc, (z + 1) * kc, row0, col0, acc);
    int M = gridDim.y * 128;
    mma_epi_raw(P + (long)z * M * N, acc, row0, col0, N);
}

__global__ void reduce_bias_kernel(const float* __restrict__ P, const float* __restrict__ bias,
                                   float* __restrict__ C, int M, int N, int nsplit, int act) {
    int i = blockIdx.x * blockDim.x + threadIdx.x;
    long sz = (long)M * N;
    if (i >= sz) return;
    float s = 0.f;
    for (int p = 0; p < nsplit; p++) s += P[(long)p * sz + i];
    s += bias[i & (N - 1)];            // N is a power of two here (1024)
    if (act) s = gelu_exact(s);
    C[i] = s;
}

// ================= bf16-split NT MMA for attention (scores/c2p/p2c, K=64) =========
// C[M,N] = A[M,K] @ B[N,K]^T. Both operands [rows][40]-padded smem; B frags are
// single aligned 32-bit LDS (NT natural for mma.row.col).
struct SmemAttNT {
    unsigned short Ahi[128][40];
    unsigned short Alo[128][40];
    unsigned short Bhi[128][40];
    unsigned short Blo[128][40];
};

__global__ __launch_bounds__(256, 2) void att_mma_kernel(
    const float* __restrict__ q, const float* __restrict__ k,
    const float* __restrict__ posk, const float* __restrict__ posq,
    float* sc, float* c2p, float* p2c) {
    __shared__ SmemAttNT sm;
    int z = blockIdx.z;
    int type = z >> 5;
    int bh = z & 31;
    int b = bh >> 4, h = bh & 15;
    const float* A = ((type == 2) ? k : q) + (long)b * Ss * Hh + (long)h * Dd;
    const float* B;
    if (type == 0)      B = k    + (long)b * Ss * Hh + (long)h * Dd;
    else if (type == 1) B = posk + (long)h * Dd;
    else                B = posq + (long)h * Dd;
    float* C = (type == 0 ? sc : (type == 1 ? c2p : p2c)) + (long)bh * Ss * 512;

    int tid  = threadIdx.x;
    int lane = tid & 31, warp = tid >> 5;
    int wm = warp & 3, wn = warp >> 2;
    int gg = lane >> 2, qq = lane & 3;
    int row0 = blockIdx.y * 128, col0 = blockIdx.x * 128;
    float acc[64] = {};

    #pragma unroll
    for (int k0 = 0; k0 < Dd; k0 += 32) {
        // A tile: 128 rows x 32 k
        #pragma unroll
        for (int i = 0; i < 4; i++) {
            int idx = i * 256 + tid;
            int m = idx >> 3, kq = (idx & 7) * 4;
            float4 av = *(const float4*)(A + (long)(row0 + m) * Hh + k0 + kq);
            unsigned short h0,h1,h2,h3,l0,l1,l2,l3;
            bfsplit(av.x,h0,l0); bfsplit(av.y,h1,l1);
            bfsplit(av.z,h2,l2); bfsplit(av.w,h3,l3);
            *(unsigned int*)&sm.Ahi[m][kq]   = (unsigned int)h0 | ((unsigned int)h1 << 16);
            *(unsigned int*)&sm.Ahi[m][kq+2] = (unsigned int)h2 | ((unsigned int)h3 << 16);
            *(unsigned int*)&sm.Alo[m][kq]   = (unsigned int)l0 | ((unsigned int)l1 << 16);
            *(unsigned int*)&sm.Alo[m][kq+2] = (unsigned int)l2 | ((unsigned int)l3 << 16);
        }
        // B tile: 128 n-rows x 32 k
        #pragma unroll
        for (int i = 0; i < 4; i++) {
            int idx = i * 256 + tid;
            int m = idx >> 3, kq = (idx & 7) * 4;
            float4 bvv = *(const float4*)(B + (long)(col0 + m) * Hh + k0 + kq);
            unsigned short h0,h1,h2,h3,l0,l1,l2,l3;
            bfsplit(bvv.x,h0,l0); bfsplit(bvv.y,h1,l1);
            bfsplit(bvv.z,h2,l2); bfsplit(bvv.w,h3,l3);
            *(unsigned int*)&sm.Bhi[m][kq]   = (unsigned int)h0 | ((unsigned int)h1 << 16);
            *(unsigned int*)&sm.Bhi[m][kq+2] = (unsigned int)h2 | ((unsigned int)h3 << 16);
            *(unsigned int*)&sm.Blo[m][kq]   = (unsigned int)l0 | ((unsigned int)l1 << 16);
            *(unsigned int*)&sm.Blo[m][kq+2] = (unsigned int)l2 | ((unsigned int)l3 << 16);
        }
        __syncthreads();

        #pragma unroll
        for (int ks = 0; ks < 32; ks += 16) {
            unsigned int ah[2][4], al[2][4];
            #pragma unroll
            for (int mt = 0; mt < 2; mt++) {
                int r  = wm * 32 + mt * 16 + gg;
                int kc = ks + 2 * qq;
                ah[mt][0] = *(unsigned int*)&sm.Ahi[r    ][kc    ];
                ah[mt][1] = *(unsigned int*)&sm.Ahi[r + 8][kc    ];
                ah[mt][2] = *(unsigned int*)&sm.Ahi[r    ][kc + 8];
                ah[mt][3] = *(unsigned int*)&sm.Ahi[r + 8][kc + 8];
                al[mt][0] = *(unsigned int*)&sm.Alo[r    ][kc    ];
                al[mt][1] = *(unsigned int*)&sm.Alo[r + 8][kc    ];
                al[mt][2] = *(unsigned int*)&sm.Alo[r    ][kc + 8];
                al[mt][3] = *(unsigned int*)&sm.Alo[r + 8][kc + 8];
            }
            #pragma unroll
            for (int nt = 0; nt < 8; nt++) {
                int n  = wn * 64 + nt * 8 + gg;
                int kb = ks + 2 * qq;
                unsigned int bh0 = *(unsigned int*)&sm.Bhi[n][kb];
                unsigned int bh1 = *(unsigned int*)&sm.Bhi[n][kb + 8];
                unsigned int bl0 = *(unsigned int*)&sm.Blo[n][kb];
                unsigned int bl1 = *(unsigned int*)&sm.Blo[n][kb + 8];
                #pragma unroll
                for (int mt = 0; mt < 2; mt++) {
                    float* c = acc + (mt * 8 + nt) * 4;
                    mma16816(c, ah[mt][0], ah[mt][1], ah[mt][2], ah[mt][3], bh0, bh1);
                    mma16816(c, ah[mt][0], ah[mt][1], ah[mt][2], ah[mt][3], bl0, bl1);
                    mma16816(c, al[mt][0], al[mt][1], al[mt][2], al[mt][3], bh0, bh1);
                }
            }
        }
        __syncthreads();
    }
    mma_epi_raw(C, acc, row0, col0, 512);
}

// ================= bf16-split NN MMA for ctx = probs @ v (K=512, N=64) ============
struct SmemCtx {
    unsigned short Ahi[128][40];
    unsigned short Alo[128][40];
    unsigned short Bhi[64][40];    // [d][s] transposed
    unsigned short Blo[64][40];
};

__global__ __launch_bounds__(256, 2) void ctx_mma_kernel(
    const float* __restrict__ sc, const float* __restrict__ v, float* __restrict__ ctx) {
    __shared__ SmemCtx sm;
    int bh = blockIdx.z;
    int b = bh >> 4, h = bh & 15;
    const float* A = sc + (long)bh * Ss * Ss;                // [512][512]
    const float* Bv = v + (long)b * Ss * Hh + (long)h * Dd;  // rows=s, cols=d, ld=Hh
    float* C = ctx + (long)b * Ss * Hh + (long)h * Dd;       // ld=Hh

    int tid  = threadIdx.x;
    int lane = tid & 31, warp = tid >> 5;
    int wm = warp & 3, wn = warp >> 2;        // 4 (m) x 2 (n of 32)
    int gg = lane >> 2, qq = lane & 3;
    int row0 = blockIdx.y * 128;
    float acc[32] = {};                       // 2 mt x 4 nt x 4

    for (int k0 = 0; k0 < Ss; k0 += 32) {
        // A tile: 128 rows x 32 k
        #pragma unroll
        for (int i = 0; i < 4; i++) {
            int idx = i * 256 + tid;
            int m = idx >> 3, kq = (idx & 7) * 4;
            float4 av = *(const float4*)(A + (long)(row0 + m) * Ss + k0 + kq);
            unsigned short h0,h1,h2,h3,l0,l1,l2,l3;
            bfsplit(av.x,h0,l0); bfsplit(av.y,h1,l1);
            bfsplit(av.z,h2,l2); bfsplit(av.w,h3,l3);
            *(unsigned int*)&sm.Ahi[m][kq]   = (unsigned int)h0 | ((unsigned int)h1 << 16);
            *(unsigned int*)&sm.Ahi[m][kq+2] = (unsigned int)h2 | ((unsigned int)h3 << 16);
            *(unsigned int*)&sm.Alo[m][kq]   = (unsigned int)l0 | ((unsigned int)l1 << 16);
            *(unsigned int*)&sm.Alo[m][kq+2] = (unsigned int)l2 | ((unsigned int)l3 << 16);
        }
        // B tile: 32 s-rows x 64 d -> transposed smem [d][s]
        #pragma unroll
        for (int i = 0; i < 2; i++) {
            int idx = i * 256 + tid;
            int kk = idx >> 4, n4 = (idx & 15) * 4;
            float4 bvv = *(const float4*)(Bv + (long)(k0 + kk) * Hh + n4);
            unsigned short h0,h1,h2,h3,l0,l1,l2,l3;
            bfsplit(bvv.x,h0,l0); bfsplit(bvv.y,h1,l1);
            bfsplit(bvv.z,h2,l2); bfsplit(bvv.w,h3,l3);
            sm.Bhi[n4+0][kk] = h0; sm.Bhi[n4+1][kk] = h1;
            sm.Bhi[n4+2][kk] = h2; sm.Bhi[n4+3][kk] = h3;
            sm.Blo[n4+0][kk] = l0; sm.Blo[n4+1][kk] = l1;
            sm.Blo[n4+2][kk] = l2; sm.Blo[n4+3][kk] = l3;
        }
        __syncthreads();

        #pragma unroll
        for (int ks = 0; ks < 32; ks += 16) {
            unsigned int ah[2][4], al[2][4];
            #pragma unroll
            for (int mt = 0; mt < 2; mt++) {
                int r  = wm * 32 + mt * 16 + gg;
                int kc = ks + 2 * qq;
                ah[mt][0] = *(unsigned int*)&sm.Ahi[r    ][kc    ];
                ah[mt][1] = *(unsigned int*)&sm.Ahi[r + 8][kc    ];
                ah[mt][2] = *(unsigned int*)&sm.Ahi[r    ][kc + 8];
                ah[mt][3] = *(unsigned int*)&sm.Ahi[r + 8][kc + 8];
                al[mt][0] = *(unsigned int*)&sm.Alo[r    ][kc    ];
                al[mt][1] = *(unsigned int*)&sm.Alo[r + 8][kc    ];
                al[mt][2] = *(unsigned int*)&sm.Alo[r    ][kc + 8];
                al[mt][3] = *(unsigned int*)&sm.Alo[r + 8][kc + 8];
            }
            #pragma unroll
            for (int nt = 0; nt < 4; nt++) {
                int n  = wn * 32 + nt * 8 + gg;
                int kb = ks + 2 * qq;
                unsigned int bh0 = *(unsigned int*)&sm.Bhi[n][kb];
                unsigned int bh1 = *(unsigned int*)&sm.Bhi[n][kb + 8];
                unsigned int bl0 = *(unsigned int*)&sm.Blo[n][kb];
                unsigned int bl1 = *(unsigned int*)&sm.Blo[n][kb + 8];
                #pragma unroll
                for (int mt = 0; mt < 2; mt++) {
                    float* c = acc + (mt * 4 + nt) * 4;
                    mma16816(c, ah[mt][0], ah[mt][1], ah[mt][2], ah[mt][3], bh0, bh1);
                    mma16816(c, ah[mt][0], ah[mt][1], ah[mt][2], ah[mt][3], bl0, bl1);
                    mma16816(c, al[mt][0], al[mt][1], al[mt][2], al[mt][3], bh0, bh1);
                }
            }
        }
        __syncthreads();
    }

    #pragma unroll
    for (int mt = 0; mt < 2; mt++)
        #pragma unroll
        for (int nt = 0; nt < 4; nt++) {
            int row = row0 + wm * 32 + mt * 16 + gg;
            int col = wn * 32 + nt * 8 + 2 * qq;
            const float* c = acc + (mt * 4 + nt) * 4;
            *(float2*)(C + (long)row * Hh + col)       = make_float2(c[0], c[1]);
            *(float2*)(C + (long)(row + 8) * Hh + col) = make_float2(c[2], c[3]);
        }
}

// ---------------- relative-position bucket indices ----------------
__global__ void idx_kernel(int* c2pidx, int* p2cidx) {
    int t = blockIdx.x * blockDim.x + threadIdx.x;
    if (t >= Ss * Ss) return;
    int q = t / Ss, k = t % Ss;
    int rel = q - k;
    const int mid = 128;
    int ap = (rel < mid && rel > -mid) ? (mid - 1) : (rel < 0 ? -rel : rel);
    int bucket;
    if (ap <= mid) {
        bucket = rel;
    } else {
        const float divisor = (float)1.3843393288235763;  // np.log(511/128) as f32
        float lp = ceilf(logf((float)ap / 128.0f) / divisor * 127.0f) + 128.0f;
        float sgn = (rel > 0) ? 1.0f : ((rel < 0) ? -1.0f : 0.0f);
        bucket = (int)(lp * sgn);
    }
    int c = bucket + SPAN;  c = c < 0 ? 0 : (c > 2 * SPAN - 1 ? 2 * SPAN - 1 : c);
    int p = -bucket + SPAN; p = p < 0 ? 0 : (p > 2 * SPAN - 1 ? 2 * SPAN - 1 : p);
    c2pidx[t] = c;
    p2cidx[t] = p;
}

// ---------------- embedding: x = LN(word_emb[ids]) * mask ----------------
__global__ void embed_kernel(const float* __restrict__ wemb, const int* __restrict__ ids,
                             const int* __restrict__ amask,
                             const float* __restrict__ s, const float* __restrict__ bb,
                             float* __restrict__ out) {
    __shared__ float red[256];
    int m = blockIdx.x, tid = threadIdx.x;
    const float* in = wemb + (long)ids[m] * Hh;
    float v[4];
    #pragma unroll
    for (int i = 0; i < 4; i++) v[i] = in[tid + i * 256];
    float sum = 0.f;
    #pragma unroll
    for (int i = 0; i < 4; i++) sum += v[i];
    float mu = block_sum(sum, red) * (1.0f / Hh);
    float var = 0.f;
    #pragma unroll
    for (int i = 0; i < 4; i++) { float d = v[i] - mu; var += d * d; }
    float vt = block_sum(var, red) * (1.0f / Hh);
    float inv = rsqrtf(vt + EPSLN);
    float mk = amask[m] ? 1.0f : 0.0f;
    #pragma unroll
    for (int i = 0; i < 4; i++) {
        int c = tid + i * 256;
        out[(long)m * Hh + c] = ((v[i] - mu) * inv * s[c] + bb[c]) * mk;
    }
}

// ---------------- plain row LayerNorm over H=1024 ----------------
__global__ void ln_kernel(const float* __restrict__ in, float* __restrict__ out,
                          const float* __restrict__ s, const float* __restrict__ bb) {
    __shared__ float red[256];
    int m = blockIdx.x, tid = threadIdx.x;
    const float* ir = in + (long)m * Hh;
    float v[4];
    #pragma unroll
    for (int i = 0; i < 4; i++) v[i] = ir[tid + i * 256];
    float sum = 0.f;
    #pragma unroll
    for (int i = 0; i < 4; i++) sum += v[i];
    float mu = block_sum(sum, red) * (1.0f / Hh);
    float var = 0.f;
    #pragma unroll
    for (int i = 0; i < 4; i++) { float d = v[i] - mu; var += d * d; }
    float vt = block_sum(var, red) * (1.0f / Hh);
    float inv = rsqrtf(vt + EPSLN);
    #pragma unroll
    for (int i = 0; i < 4; i++) {
        int c = tid + i * 256;
        out[(long)m * Hh + c] = (v[i] - mu) * inv * s[c] + bb[c];
    }
}

// ---------------- residual + LayerNorm: h = LN(h + y) ----------------
__global__ void add_ln_kernel(float* __restrict__ h, const float* __restrict__ y,
                              const float* __restrict__ s, const float* __restrict__ bb) {
    __shared__ float red[256];
    int m = blockIdx.x, tid = threadIdx.x;
    long base = (long)m * Hh;
    float v[4];
    #pragma unroll
    for (int i = 0; i < 4; i++) { int c = tid + i * 256; v[i] = h[base + c] + y[base + c]; }
    float sum = 0.f;
    #pragma unroll
    for (int i = 0; i < 4; i++) sum += v[i];
    float mu = block_sum(sum, red) * (1.0f / Hh);
    float var = 0.f;
    #pragma unroll
    for (int i = 0; i < 4; i++) { float d = v[i] - mu; var += d * d; }
    float vt = block_sum(var, red) * (1.0f / Hh);
    float inv = rsqrtf(vt + EPSLN);
    #pragma unroll
    for (int i = 0; i < 4; i++) {
        int c = tid + i * 256;
        h[base + c] = (v[i] - mu) * inv * s[c] + bb[c];
    }
}

// ---------------- small-N SGEMM (decoder head, N=14) ----------------
#define BM 64
#define BN 64
#define BK 16
__global__ void gemm_bias_kernel(const float* __restrict__ A, const float* __restrict__ W,
                                 const float* __restrict__ bias, float* __restrict__ C,
                                 int M, int N, int K, int act) {
    __shared__ float As[BK][BM];
    __shared__ float Bs[BK][BN];
    int tid = threadIdx.x;
    int tx = tid & 15, ty = tid >> 4;
    int row0 = blockIdx.y * BM, col0 = blockIdx.x * BN;
    float acc[4][4] = {};
    for (int k0 = 0; k0 < K; k0 += BK) {
        #pragma unroll
        for (int i = 0; i < 4; i++) {
            int idx = tid + i * 256;
            int kk = idx >> 6, mm = idx & 63;
            As[kk][mm] = A[(long)(row0 + mm) * K + k0 + kk];
        }
        #pragma unroll
        for (int i = 0; i < 4; i++) {
            int idx = tid + i * 256;
            int kk = idx >> 6, nn = idx & 63;
            int col = col0 + nn;
            Bs[kk][nn] = (col < N) ? W[(long)(k0 + kk) * N + col] : 0.0f;
        }
        __syncthreads();
        #pragma unroll
        for (int kk = 0; kk < BK; kk++) {
            float a[4], b[4];
            #pragma unroll
            for (int i = 0; i < 4; i++) a[i] = As[kk][ty * 4 + i];
            #pragma unroll
            for (int j = 0; j < 4; j++) b[j] = Bs[kk][tx * 4 + j];
            #pragma unroll
            for (int i = 0; i < 4; i++)
                #pragma unroll
                for (int j = 0; j < 4; j++)
                    acc[i][j] += a[i] * b[j];
        }
        __syncthreads();
    }
    #pragma unroll
    for (int i = 0; i < 4; i++) {
        int r = row0 + ty * 4 + i;
        #pragma unroll
        for (int j = 0; j < 4; j++) {
            int c = col0 + tx * 4 + j;
            if (c < N) {
                float v = acc[i][j] + bias[c];
                if (act == 1) v = gelu_exact(v);
                C[(long)r * N + c] = v;
            }
        }
    }
}

// ---------------- fused gather + scale + mask + softmax (in place) ----
__global__ void softmax_kernel(float* __restrict__ scores,
                               const float* __restrict__ c2p, const float* __restrict__ p2c,
                               const int* __restrict__ ic2p, const int* __restrict__ ip2c,
                               const int* __restrict__ amask) {
    __shared__ float sm[Ss];
    __shared__ float red[256];
    int q  = blockIdx.x;
    int bh = blockIdx.y;
    int b  = bh / NHh;
    int tid = threadIdx.x;
    const float inv_scale = 0.07216878364870322f;  // 1/sqrt(3*D)
    int maskq = amask[b * Ss + q];
    float* row = scores + ((long)bh * Ss + q) * Ss;
    const float* c2pr = c2p + ((long)bh * Ss + q) * Rr;
    const float* p2cb = p2c + (long)bh * Ss * Rr;

    for (int k = tid; k < Ss; k += 256) {
        float s;
        if (maskq && amask[b * Ss + k]) {
            s = (row[k] + c2pr[ic2p[q * Ss + k]] + p2cb[(long)k * Rr + ip2c[k * Ss + q]]) * inv_scale;
        } else {
            s = -INFINITY;
        }
        sm[k] = s;
    }
    __syncthreads();
    float mx = -INFINITY;
    for (int k = tid; k < Ss; k += 256) mx = fmaxf(mx, sm[k]);
    red[tid] = mx; __syncthreads();
    #pragma unroll
    for (int s = 128; s > 0; s >>= 1) {
        if (tid < s) red[tid] = fmaxf(red[tid], red[tid + s]);
        __syncthreads();
    }
    mx = red[0]; __syncthreads();
    if (mx == -INFINITY) {
        for (int k = tid; k < Ss; k += 256) row[k] = 0.0f;
        return;
    }
    float sum = 0.f;
    for (int k = tid; k < Ss; k += 256) {
        float e = expf(sm[k] - mx);
        sm[k] = e;
        sum += e;
    }
    float tot = block_sum(sum, red);
    float inv = 1.0f / tot;
    for (int k = tid; k < Ss; k += 256) row[k] = sm[k] * inv;
}

// ---------------- loss + output assembly ----------------
__global__ void finalize_kernel(const float* __restrict__ logits, const int* __restrict__ labels,
                                const int* __restrict__ amask, float* __restrict__ out,
                                int out_size) {
    __shared__ float r1[256], r2[256];
    int tid = threadIdx.x;
    float ls = 0.f, ms = 0.f;
    for (int m = tid; m < Mm; m += 256) {
        const float* lr = logits + m * NCc;
        float mx = lr[0];
        #pragma unroll
        for (int c = 1; c < NCc; c++) mx = fmaxf(mx, lr[c]);
        float se = 0.f;
        #pragma unroll
        for (int c = 0; c < NCc; c++) se += expf(lr[c] - mx);
        float lse = logf(se) + mx;
        float nll = lse - lr[labels[m]];
        float mk = amask[m] ? 1.0f : 0.0f;
        ls += nll * mk;
        ms += mk;
    }
    r1[tid] = ls; r2[tid] = ms; __syncthreads();
    #pragma unroll
    for (int s = 128; s > 0; s >>= 1) {
        if (tid < s) { r1[tid] += r1[tid + s]; r2[tid] += r2[tid + s]; }
        __syncthreads();
    }
    float loss = r1[0] / fmaxf(r2[0], 1.0f);
    const int total = Mm * NCc;
    for (int i = tid; i < out_size; i += 256)
        out[i] = (i < total) ? logits[i] : loss;
}

// ---------------- host driver ----------------
extern "C" void kernel_launch(void* const* d_in, const int* in_sizes, int n_in,
                              void* d_out, int out_size) {
    const float* word_emb = (const float*)d_in[0];
    const float* emb_ln_s = (const float*)d_in[1];
    const float* emb_ln_b = (const float*)d_in[2];
    const float* rel_emb  = (const float*)d_in[3];
    const float* rel_ln_s = (const float*)d_in[4];
    const float* rel_ln_b = (const float*)d_in[5];
    const float* Wq = (const float*)d_in[6];
    const float* bq = (const float*)d_in[7];
    const float* Wk = (const float*)d_in[8];
    const float* bk = (const float*)d_in[9];
    const float* Wv = (const float*)d_in[10];
    const float* bv = (const float*)d_in[11];
    const float* Wo = (const float*)d_in[12];
    const float* bo = (const float*)d_in[13];
    const float* ln1_s = (const float*)d_in[14];
    const float* ln1_b = (const float*)d_in[15];
    const float* W1 = (const float*)d_in[16];
    const float* b1 = (const float*)d_in[17];
    const float* W2 = (const float*)d_in[18];
    const float* b2 = (const float*)d_in[19];
    const float* ln2_s = (const float*)d_in[20];
    const float* ln2_b = (const float*)d_in[21];
    const float* Wt = (const float*)d_in[22];
    const float* bt = (const float*)d_in[23];
    const float* tln_s = (const float*)d_in[24];
    const float* tln_b = (const float*)d_in[25];
    const float* Wd = (const float*)d_in[26];
    const float* bd = (const float*)d_in[27];
    const int* input_ids = (const int*)d_in[28];
    const int* amask     = (const int*)d_in[29];
    const int* labels    = (const int*)d_in[30];

    static bool init = false;
    static float *x, *rel, *q, *k, *v, *posk, *posq, *sc, *c2p, *p2c, *ctx, *tmp, *ff, *t, *part, *logits;
    static int *ic2p, *ip2c;
    if (!init) {
        cudaGetSymbolAddress((void**)&x, g_x);
        cudaGetSymbolAddress((void**)&rel, g_rel);
        cudaGetSymbolAddress((void**)&q, g_q);
        cudaGetSymbolAddress((void**)&k, g_k);
        cudaGetSymbolAddress((void**)&v, g_v);
        cudaGetSymbolAddress((void**)&posk, g_posk);
        cudaGetSymbolAddress((void**)&posq, g_posq);
        cudaGetSymbolAddress((void**)&sc, g_sc);
        cudaGetSymbolAddress((void**)&c2p, g_c2p);
        cudaGetSymbolAddress((void**)&p2c, g_p2c);
        cudaGetSymbolAddress((void**)&ctx, g_ctx);
        cudaGetSymbolAddress((void**)&tmp, g_tmp);
        cudaGetSymbolAddress((void**)&ff, g_ff);
        cudaGetSymbolAddress((void**)&t, g_t);
        cudaGetSymbolAddress((void**)&part, g_part);
        cudaGetSymbolAddress((void**)&logits, g_logits);
        cudaGetSymbolAddress((void**)&ic2p, g_ic2p);
        cudaGetSymbolAddress((void**)&ip2c, g_ip2c);
        init = true;
    }

    // precompute
    idx_kernel<<<(Ss * Ss + 255) / 256, 256>>>(ic2p, ip2c);
    ln_kernel<<<Rr, 256>>>(rel_emb, rel, rel_ln_s, rel_ln_b);
    embed_kernel<<<Mm, 256>>>(word_emb, input_ids, amask, emb_ln_s, emb_ln_b, x);

    for (int l = 0; l < Ll; l++) {
        const float* Wq_l = Wq + (long)l * Hh * Hh;  const float* bq_l = bq + l * Hh;
        const float* Wk_l = Wk + (long)l * Hh * Hh;  const float* bk_l = bk + l * Hh;
        const float* Wv_l = Wv + (long)l * Hh * Hh;  const float* bv_l = bv + l * Hh;
        const float* Wo_l = Wo + (long)l * Hh * Hh;  const float* bo_l = bo + l * Hh;
        const float* W1_l = W1 + (long)l * Hh * FFf; const float* b1_l = b1 + l * FFf;
        const float* W2_l = W2 + (long)l * FFf * Hh; const float* b2_l = b2 + l * Hh;

        // q/k/v + pos_k/pos_q on tensor cores (one launch)
        qkvpos_mma<<<dim3(8, 8, 5), 256>>>(
            x, rel, Wq_l, Wk_l, Wv_l, bq_l, bk_l, bv_l, q, k, v, posk, posq);

        // scores + c2p + p2c on tensor cores (one NT launch, 1536 blocks)
        att_mma_kernel<<<dim3(4, 4, 96), 256>>>(q, k, posk, posq, sc, c2p, p2c);

        softmax_kernel<<<dim3(Ss, Bb * NHh), 256>>>(sc, c2p, p2c, ic2p, ip2c, amask);

        // ctx[b,q,h,d] = probs @ v on tensor cores
        ctx_mma_kernel<<<dim3(1, 4, Bb * NHh), 256>>>(sc, v, ctx);

        // o-projection on tensor cores: split-K 4
        gemm_mma_split<<<dim3(8, 8, 4), 256>>>(ctx, Wo_l, part, Hh, Hh, 4);
        reduce_bias_kernel<<<(Mm * Hh + 255) / 256, 256>>>(part, bo_l, tmp, Mm, Hh, 4, 0);
        add_ln_kernel<<<Mm, 256>>>(x, tmp, ln1_s + l * Hh, ln1_b + l * Hh);

        // FFN on tensor cores
        gemm_mma<<<dim3(32, 8), 256>>>(x, W1_l, b1_l, ff, FFf, Hh, 1);
        gemm_mma_split<<<dim3(8, 8, 4), 256>>>(ff, W2_l, part, Hh, FFf, 4);
        reduce_bias_kernel<<<(Mm * Hh + 255) / 256, 256>>>(part, b2_l, tmp, Mm, Hh, 4, 0);
        add_ln_kernel<<<Mm, 256>>>(x, tmp, ln2_s + l * Hh, ln2_b + l * Hh);
    }

    // head: transform (GELU) on tensor cores via split-K 4, then LN, then decoder
    gemm_mma_split<<<dim3(8, 8, 4), 256>>>(x, Wt, part, Hh, Hh, 4);
    reduce_bias_kernel<<<(Mm * Hh + 255) / 256, 256>>>(part, bt, t, Mm, Hh, 4, 1);
    ln_kernel<<<Mm, 256>>>(t, t, tln_s, tln_b);
    gemm_bias_kernel<<<dim3((NCc + BN - 1) / BN, Mm / BM), 256>>>(t, Wd, bd, logits, Mm, NCc, Hh, 0);

    finalize_kernel<<<1, 256>>>(logits, labels, amask, (float*)d_out, out_size);
}